// round 10
// baseline (speedup 1.0000x reference)
#include <cuda_runtime.h>
#include <math.h>

#define Bb 8
#define Cc 256
#define Ll 512
#define NG 32
#define NH 8
#define Ee 1024
#define NTOK (Bb*Cc)

typedef unsigned long long u64;

// ---------------- f32x2 helpers ----------------
__device__ __forceinline__ u64 fma2(u64 a, u64 b, u64 c) {
    u64 d; asm("fma.rn.f32x2 %0, %1, %2, %3;" : "=l"(d) : "l"(a), "l"(b), "l"(c)); return d;
}
__device__ __forceinline__ u64 mul2(u64 a, u64 b) {
    u64 d; asm("mul.rn.f32x2 %0, %1, %2;" : "=l"(d) : "l"(a), "l"(b)); return d;
}
__device__ __forceinline__ u64 add2(u64 a, u64 b) {
    u64 d; asm("add.rn.f32x2 %0, %1, %2;" : "=l"(d) : "l"(a), "l"(b)); return d;
}
__device__ __forceinline__ u64 pk2(float x, float y) {
    u64 d; asm("mov.b64 %0, {%1, %2};" : "=l"(d) : "r"(__float_as_uint(x)), "r"(__float_as_uint(y))); return d;
}
__device__ __forceinline__ float2 unpk2(u64 a) {
    unsigned int x, y; asm("mov.b64 {%0, %1}, %2;" : "=r"(x), "=r"(y) : "l"(a));
    return make_float2(__uint_as_float(x), __uint_as_float(y));
}

// ---------------- scratch ----------------
__device__ float g_S1[Bb*Cc*Ll];
__device__ float g_S2[Bb*Cc*Ll];
__device__ float g_S3[Bb*Cc*Ll];
__device__ float g_T [Bb*Ll*768];          // Q | K | V, each 8*8*512*32 = 1048576 floats
__device__ float g_rawsum[Bb*Ee];
__device__ int   g_cnt1[Bb*Ee];
__device__ int   g_idx1[NTOK];
__device__ int   g_idx2[NTOK];
__device__ float g_g1[NTOK];
__device__ float g_g2[NTOK];
__device__ int   g_ecnt[Ee];
__device__ int   g_elist[Ee*64];
__device__ float g_eout[NTOK*2*512];

__device__ __forceinline__ float gelu_f(float x) {
    return 0.5f * x * (1.0f + erff(x * 0.70710678118654752f));
}

// ---------------- fused groupnorm (+opt add) + gelu: one CTA per (b,g) ----------------
__global__ __launch_bounds__(512) void gn_k(const float* __restrict__ in, const float* __restrict__ in2,
                                            const float* __restrict__ sc, const float* __restrict__ bi,
                                            float* __restrict__ out) {
    __shared__ float4 buf[1024];
    __shared__ float rs[16], rq[16];
    int bg = blockIdx.x, tid = threadIdx.x;
    const float4* p  = (const float4*)(in + bg * 4096);
    const float4* p2 = in2 ? (const float4*)(in2 + bg * 4096) : nullptr;
    float s = 0.f, q = 0.f;
    #pragma unroll
    for (int r = 0; r < 2; r++) {
        int i = tid + r * 512;
        float4 v = p[i];
        if (p2) {
            float4 w = p2[i];
            v.x += w.x; v.y += w.y; v.z += w.z; v.w += w.w;
        }
        buf[i] = v;
        s += v.x + v.y + v.z + v.w;
        q += v.x*v.x + v.y*v.y + v.z*v.z + v.w*v.w;
    }
    #pragma unroll
    for (int o = 16; o > 0; o >>= 1) {
        s += __shfl_down_sync(0xffffffffu, s, o);
        q += __shfl_down_sync(0xffffffffu, q, o);
    }
    if ((tid & 31) == 0) { rs[tid >> 5] = s; rq[tid >> 5] = q; }
    __syncthreads();
    if (tid < 32) {
        float s2 = (tid < 16) ? rs[tid] : 0.f;
        float q2 = (tid < 16) ? rq[tid] : 0.f;
        #pragma unroll
        for (int o = 8; o > 0; o >>= 1) {
            s2 += __shfl_down_sync(0xffffffffu, s2, o);
            q2 += __shfl_down_sync(0xffffffffu, q2, o);
        }
        if (tid == 0) {
            float mean = s2 * (1.f / 4096.f);
            float var  = q2 * (1.f / 4096.f) - mean * mean;
            rs[0] = mean;
            rq[0] = rsqrtf(var + 1e-5f);
        }
    }
    __syncthreads();
    float mean = rs[0], rstd = rq[0];
    float4* op = (float4*)(out + bg * 4096);
    int cbase = (bg & 31) * 8;
    #pragma unroll
    for (int r = 0; r < 2; r++) {
        int i = tid + r * 512;
        int c = cbase + (i >> 7);
        float a = rstd * sc[c];
        float b = bi[c] - mean * a;
        float4 v = buf[i];
        v.x = gelu_f(v.x * a + b);
        v.y = gelu_f(v.y * a + b);
        v.z = gelu_f(v.z * a + b);
        v.w = gelu_f(v.w * a + b);
        op[i] = v;
    }
}

// ---------------- conv1d k=3: 16 co per block, 256 threads, 1 l per thread, f32x2 ----------------
// grid: (2 l-tiles of 256, Cout/16, 8 batch), 256 threads
__global__ __launch_bounds__(256) void conv16_k(
    const float* __restrict__ in, const float* __restrict__ w, const float* __restrict__ bias,
    const float* __restrict__ residA, const float* __restrict__ residB,
    float* __restrict__ out, int Cout) {
    __shared__ float4 ws4[256 * 3 * 4];          // [ci][tap][4 x float4 of co] = 48KB
    float* wsf = (float*)ws4;
    int b = blockIdx.z, co0 = blockIdx.y * 16;
    int l = blockIdx.x * 256 + threadIdx.x;
    for (int i = threadIdx.x; i < 16 * 768; i += 256) {
        int r = i >> 4, cl = i & 15;
        wsf[i] = w[(co0 + cl) * 768 + r];
    }
    __syncthreads();
    u64 acc[8];
    #pragma unroll
    for (int p = 0; p < 8; p++) acc[p] = pk2(bias[co0 + 2*p], bias[co0 + 2*p + 1]);
    const float* ip = in + b * 256 * 512;
    const ulonglong2* wd2 = (const ulonglong2*)wsf;
    #pragma unroll 2
    for (int ci = 0; ci < 256; ci++) {
        const float* row = ip + ci * 512;
        float xm = (l > 0)   ? __ldg(row + l - 1) : 0.f;
        float x0 = __ldg(row + l);
        float xp = (l < 511) ? __ldg(row + l + 1) : 0.f;
        u64 um = pk2(xm, xm), u0 = pk2(x0, x0), up = pk2(xp, xp);
        const ulonglong2* wp = wd2 + ci * 12;
        #pragma unroll
        for (int j = 0; j < 4; j++) {
            ulonglong2 w0 = wp[j];
            ulonglong2 w1 = wp[4 + j];
            ulonglong2 w2 = wp[8 + j];
            acc[2*j]   = fma2(um, w0.x, acc[2*j]);
            acc[2*j]   = fma2(u0, w1.x, acc[2*j]);
            acc[2*j]   = fma2(up, w2.x, acc[2*j]);
            acc[2*j+1] = fma2(um, w0.y, acc[2*j+1]);
            acc[2*j+1] = fma2(u0, w1.y, acc[2*j+1]);
            acc[2*j+1] = fma2(up, w2.y, acc[2*j+1]);
        }
    }
    int base = (b * Cout + co0) * 512 + l;
    #pragma unroll
    for (int p = 0; p < 8; p++) {
        float2 v = unpk2(acc[p]);
        int o0 = base + (2*p)     * 512;
        int o1 = base + (2*p + 1) * 512;
        float r0 = 0.f, r1 = 0.f;
        if (residA) {
            r0 = residA[o0]; r1 = residA[o1];
            if (residB) { r0 += residB[o0]; r1 += residB[o1]; }
        }
        out[o0] = v.x + r0;
        out[o1] = v.y + r1;
    }
}

// ---------------- QKV: computes tile, stages through smem, writes Q/K/V[b,h,l,32] ----------------
#define QKV_GSTR 545
__global__ __launch_bounds__(384) void qkv_k(const float* __restrict__ x, const float* __restrict__ w1,
                                             const float* __restrict__ b1, float* __restrict__ qkv) {
    extern __shared__ float sm[];
    int b = blockIdx.x, l0 = blockIdx.y * 32;
    for (int i = threadIdx.x; i < 256 * 32; i += 384) {
        int c = i >> 5, j = i & 31;
        sm[i] = x[(b * 256 + c) * 512 + l0 + j];
    }
    __syncthreads();
    int f = threadIdx.x;
    u64 A[16], B[16];
    {
        u64 ba = pk2(b1[f], b1[f]);
        u64 bb = pk2(b1[f + 384], b1[f + 384]);
        #pragma unroll
        for (int k = 0; k < 16; k++) { A[k] = ba; B[k] = bb; }
    }
    for (int c = 0; c < 256; c++) {
        float wa = w1[c * 768 + f];
        float wb = w1[c * 768 + f + 384];
        u64 ua = pk2(wa, wa), ub = pk2(wb, wb);
        const u64* xr = (const u64*)(sm + c * 32);
        #pragma unroll
        for (int k = 0; k < 16; k++) {
            u64 xv = xr[k];
            A[k] = fma2(xv, ua, A[k]);
            B[k] = fma2(xv, ub, B[k]);
        }
    }
    __syncthreads();
    int dd = f / 24, g = f - dd * 24;
    #pragma unroll
    for (int half = 0; half < 2; half++) {
        u64* R = half ? B : A;
        #pragma unroll
        for (int k = 0; k < 16; k++) {
            float2 v = unpk2(R[k]);
            sm[g * QKV_GSTR + (2*k)     * 17 + dd] = v.x;
            sm[g * QKV_GSTR + (2*k + 1) * 17 + dd] = v.y;
        }
        __syncthreads();
        #pragma unroll
        for (int rep = 0; rep < 2; rep++) {
            int j = threadIdx.x + rep * 384;
            int gg = j >> 5, l = j & 31;
            int h = gg / 3, kk = gg - h * 3;
            const float* srow = sm + gg * QKV_GSTR + l * 17;
            float4* dp = (float4*)(qkv + kk * 1048576 + (((b * 8) + h) * 512 + l0 + l) * 32 + half * 16);
            #pragma unroll
            for (int q4 = 0; q4 < 4; q4++)
                dp[q4] = make_float4(srow[q4*4], srow[q4*4+1], srow[q4*4+2], srow[q4*4+3]);
        }
        __syncthreads();
    }
}

// ---------------- attention: grid (b, h, 4 q-tiles), 128 threads, coalesced K/V fill ----------------
__global__ __launch_bounds__(128) void attn_k(const float* __restrict__ qkv, float* __restrict__ O) {
    extern __shared__ float sm[];
    float* Kf = sm;
    float* Vf = sm + 512 * 32;
    int b = blockIdx.x, h = blockIdx.y, qt = blockIdx.z, tid = threadIdx.x;
    int bh = b * 8 + h;
    {
        const float4* Ks = (const float4*)(qkv + 1048576 + bh * 16384);
        const float4* Vs = (const float4*)(qkv + 2097152 + bh * 16384);
        float4* Kd = (float4*)Kf;
        float4* Vd = (float4*)Vf;
        for (int i = tid; i < 4096; i += 128) {
            Kd[i] = Ks[i];
            Vd[i] = Vs[i];
        }
    }
    __syncthreads();
    int q = qt * 128 + tid;
    const float scale = 0.17677669529663687f;
    u64 q2[16];
    {
        const float* qb = qkv + (bh * 512 + q) * 32;
        #pragma unroll
        for (int i = 0; i < 16; i++)
            q2[i] = pk2(qb[2*i] * scale, qb[2*i + 1] * scale);
    }
    const u64* K2 = (const u64*)Kf;
    const u64* V2 = (const u64*)Vf;
    float m = -1e30f, s = 0.f;
    u64 acc2[16];
    #pragma unroll
    for (int i = 0; i < 16; i++) acc2[i] = 0ull;
    #pragma unroll 2
    for (int k = 0; k < 512; k++) {
        const u64* kr = K2 + k * 16;
        u64 d0 = mul2(q2[0], kr[0]);
        u64 d1 = mul2(q2[1], kr[1]);
        u64 d2 = mul2(q2[2], kr[2]);
        u64 d3 = mul2(q2[3], kr[3]);
        #pragma unroll
        for (int i = 4; i < 16; i += 4) {
            d0 = fma2(q2[i],     kr[i],     d0);
            d1 = fma2(q2[i + 1], kr[i + 1], d1);
            d2 = fma2(q2[i + 2], kr[i + 2], d2);
            d3 = fma2(q2[i + 3], kr[i + 3], d3);
        }
        d0 = add2(d0, d1);
        d2 = add2(d2, d3);
        d0 = add2(d0, d2);
        float2 dd = unpk2(d0);
        float dot = dd.x + dd.y;
        const u64* vr = V2 + k * 16;
        if (dot <= m) {
            float p = __expf(dot - m);
            s += p;
            u64 p2 = pk2(p, p);
            #pragma unroll
            for (int i = 0; i < 16; i++) acc2[i] = fma2(p2, vr[i], acc2[i]);
        } else {
            float corr = __expf(m - dot);
            m = dot;
            s = s * corr + 1.f;
            u64 c2 = pk2(corr, corr);
            #pragma unroll
            for (int i = 0; i < 16; i++) acc2[i] = fma2(acc2[i], c2, vr[i]);
        }
    }
    float inv = 1.f / s;
    float* op = O + (b * 512 + q) * 256 + h;
    #pragma unroll
    for (int i = 0; i < 16; i++) {
        float2 v = unpk2(acc2[i]);
        op[(2*i)     * 8] = v.x * inv;
        op[(2*i + 1) * 8] = v.y * inv;
    }
}

// ---------------- out projection: 128 threads, 2 co per thread, f32x2 over l-pairs ----------------
__global__ __launch_bounds__(128) void oproj_k(const float* __restrict__ O, const float* __restrict__ w2,
                                               const float* __restrict__ b2, const float* __restrict__ emb,
                                               float* __restrict__ out) {
    __shared__ float os[256][36];
    int b = blockIdx.x, l0 = blockIdx.y * 32;
    for (int i = threadIdx.x; i < 32 * 256; i += 128) {
        int c = i & 255, j = i >> 8;
        os[c][j] = O[(b * 512 + l0 + j) * 256 + c];
    }
    __syncthreads();
    int co = threadIdx.x;
    u64 A[16], B[16];
    {
        u64 ba = pk2(b2[co], b2[co]);
        u64 bb = pk2(b2[co + 128], b2[co + 128]);
        #pragma unroll
        for (int k = 0; k < 16; k++) { A[k] = ba; B[k] = bb; }
    }
    for (int c = 0; c < 256; c++) {
        float wa = w2[c * 256 + co];
        float wb = w2[c * 256 + co + 128];
        u64 ua = pk2(wa, wa), ub = pk2(wb, wb);
        const u64* xr = (const u64*)os[c];
        #pragma unroll
        for (int k = 0; k < 16; k++) {
            u64 xv = xr[k];
            A[k] = fma2(xv, ua, A[k]);
            B[k] = fma2(xv, ub, B[k]);
        }
    }
    #pragma unroll
    for (int k = 0; k < 16; k++) {
        float2 va = unpk2(A[k]);
        float2 vb = unpk2(B[k]);
        int oi  = (b * 256 + co) * 512 + l0 + 2*k;
        int oi2 = (b * 256 + co + 128) * 512 + l0 + 2*k;
        out[oi]      = va.x + emb[oi];
        out[oi + 1]  = va.y + emb[oi + 1];
        out[oi2]     = vb.x + emb[oi2];
        out[oi2 + 1] = vb.y + emb[oi2 + 1];
    }
}

// ---------------- zero rawsum + ecnt ----------------
__global__ void zero_k() {
    int i = blockIdx.x * 256 + threadIdx.x;
    if (i < Bb * Ee) g_rawsum[i] = 0.f;
    else if (i < Bb * Ee + Ee) g_ecnt[i - Bb * Ee] = 0;
}

// ---------------- gating: 4 tokens per block ----------------
__global__ __launch_bounds__(256) void gate_k(const float* __restrict__ X, const float* __restrict__ wg) {
    __shared__ float xv[4][512];
    __shared__ float red[256];
    __shared__ int redi[256];
    int t0 = blockIdx.x * 4, tid = threadIdx.x, b = t0 >> 8;
    for (int i = tid; i < 4 * 512; i += 256) {
        int tok = i >> 9, d = i & 511;
        xv[tok][d] = X[(t0 + tok) * 512 + d];
    }
    __syncthreads();
    int e0 = tid * 4;
    float acc[4][4];
    #pragma unroll
    for (int tk = 0; tk < 4; tk++)
        #pragma unroll
        for (int j = 0; j < 4; j++) acc[tk][j] = 0.f;
    for (int d = 0; d < 512; d++) {
        float4 w = *(const float4*)(wg + d * 1024 + e0);
        #pragma unroll
        for (int tk = 0; tk < 4; tk++) {
            float xd = xv[tk][d];
            acc[tk][0] += xd * w.x; acc[tk][1] += xd * w.y;
            acc[tk][2] += xd * w.z; acc[tk][3] += xd * w.w;
        }
    }
    float rs[4] = {0.f, 0.f, 0.f, 0.f};
    for (int tk = 0; tk < 4; tk++) {
        int t = t0 + tk;
        float l0 = acc[tk][0], l1 = acc[tk][1], l2 = acc[tk][2], l3 = acc[tk][3];
        float lm = fmaxf(fmaxf(l0, l1), fmaxf(l2, l3));
        red[tid] = lm; __syncthreads();
        for (int s = 128; s > 0; s >>= 1) { if (tid < s) red[tid] = fmaxf(red[tid], red[tid + s]); __syncthreads(); }
        float gmax = red[0]; __syncthreads();
        float e_0 = __expf(l0 - gmax), e_1 = __expf(l1 - gmax), e_2 = __expf(l2 - gmax), e_3 = __expf(l3 - gmax);
        red[tid] = e_0 + e_1 + e_2 + e_3; __syncthreads();
        for (int s = 128; s > 0; s >>= 1) { if (tid < s) red[tid] += red[tid + s]; __syncthreads(); }
        float inv = 1.f / red[0]; __syncthreads();
        rs[0] += e_0 * inv; rs[1] += e_1 * inv; rs[2] += e_2 * inv; rs[3] += e_3 * inv;
        float bv = l0; int bi = e0;
        if (l1 > bv) { bv = l1; bi = e0 + 1; }
        if (l2 > bv) { bv = l2; bi = e0 + 2; }
        if (l3 > bv) { bv = l3; bi = e0 + 3; }
        red[tid] = bv; redi[tid] = bi; __syncthreads();
        for (int s = 128; s > 0; s >>= 1) {
            if (tid < s) {
                float ov = red[tid + s]; int oi = redi[tid + s];
                if (ov > red[tid] || (ov == red[tid] && oi < redi[tid])) { red[tid] = ov; redi[tid] = oi; }
            }
            __syncthreads();
        }
        float v1 = red[0]; int i1 = redi[0]; __syncthreads();
        float m0 = l0, m1 = l1, m2 = l2, m3 = l3;
        if      (i1 == e0)     m0 = -3e38f;
        else if (i1 == e0 + 1) m1 = -3e38f;
        else if (i1 == e0 + 2) m2 = -3e38f;
        else if (i1 == e0 + 3) m3 = -3e38f;
        bv = m0; bi = e0;
        if (m1 > bv) { bv = m1; bi = e0 + 1; }
        if (m2 > bv) { bv = m2; bi = e0 + 2; }
        if (m3 > bv) { bv = m3; bi = e0 + 3; }
        red[tid] = bv; redi[tid] = bi; __syncthreads();
        for (int s = 128; s > 0; s >>= 1) {
            if (tid < s) {
                float ov = red[tid + s]; int oi = redi[tid + s];
                if (ov > red[tid] || (ov == red[tid] && oi < redi[tid])) { red[tid] = ov; redi[tid] = oi; }
            }
            __syncthreads();
        }
        if (tid == 0) {
            float v2 = red[0]; int i2 = redi[0];
            float ga = __expf(v1 - gmax) * inv;
            float gb = __expf(v2 - gmax) * inv;
            float den = ga + gb + 1e-9f;
            g_idx1[t] = i1; g_idx2[t] = i2;
            g_g1[t] = ga / den; g_g2[t] = gb / den;
        }
        __syncthreads();
    }
    #pragma unroll
    for (int j = 0; j < 4; j++)
        if (rs[j] != 0.f) atomicAdd(&g_rawsum[b * 1024 + e0 + j], rs[j]);
}

// ---------------- capacity walk ----------------
__global__ void cap_k() {
    __shared__ int c1[1024], c2[1024];
    int b = blockIdx.x;
    for (int i = threadIdx.x; i < 1024; i += 256) { c1[i] = 0; c2[i] = 0; }
    __syncthreads();
    if (threadIdx.x == 0) {
        for (int n = 0; n < 256; n++) {
            int t = b * 256 + n; int e = g_idx1[t];
            if (c1[e] >= 4) g_g1[t] = 0.f;
            c1[e]++;
        }
        for (int n = 0; n < 256; n++) {
            int t = b * 256 + n; int e = g_idx2[t];
            int p = c2[e] + min(c1[e], 4);
            if (p >= 4) g_g2[t] = 0.f;
            c2[e]++;
        }
    }
    __syncthreads();
    for (int i = threadIdx.x; i < 1024; i += 256) g_cnt1[b * 1024 + i] = c1[i];
}

// ---------------- aux loss ----------------
__global__ void loss_k(float* __restrict__ aux) {
    __shared__ float red[256];
    float s = 0.f;
    for (int i = threadIdx.x; i < Bb * Ee; i += 256) s += g_rawsum[i] * (float)g_cnt1[i];
    red[threadIdx.x] = s; __syncthreads();
    for (int st = 128; st > 0; st >>= 1) { if (threadIdx.x < st) red[threadIdx.x] += red[threadIdx.x + st]; __syncthreads(); }
    if (threadIdx.x == 0) *aux = red[0] * (0.01f * (float)Ee / ((float)Bb * 256.f * 256.f));
}

// ---------------- scatter tokens to expert lists ----------------
__global__ void scatter_k() {
    int t = blockIdx.x * 256 + threadIdx.x;
    if (t >= NTOK) return;
    if (g_g1[t] != 0.f) {
        int e = g_idx1[t];
        int p = atomicAdd(&g_ecnt[e], 1);
        g_elist[e * 64 + p] = t * 2;
    }
    if (g_g2[t] != 0.f) {
        int e = g_idx2[t];
        int p = atomicAdd(&g_ecnt[e], 1);
        g_elist[e * 64 + p] = t * 2 + 1;
    }
}

// ---------------- expert compute: one block per expert ----------------
__global__ __launch_bounds__(256) void expert_k(const float* __restrict__ X, const float* __restrict__ w1,
                                                const float* __restrict__ w2) {
    int e = blockIdx.x;
    int nt = g_ecnt[e];
    if (nt == 0) return;
    __shared__ float xs[8][512];
    __shared__ float hs[8][32];
    int tid = threadIdx.x;
    for (int base = 0; base < nt; base += 8) {
        int nb = min(8, nt - base);
        for (int i = tid; i < nb * 512; i += 256) {
            int ti = i >> 9, d = i & 511;
            int a = g_elist[e * 64 + base + ti];
            xs[ti][d] = X[(a >> 1) * 512 + d];
        }
        __syncthreads();
        int ti = tid >> 5, hid = tid & 31;
        if (ti < nb) {
            float hv = 0.f;
            const float* wp = w1 + (size_t)e * 512 * 32 + hid;
            const float* xr = xs[ti];
            #pragma unroll 8
            for (int d = 0; d < 512; d++) hv += xr[d] * wp[d * 32];
            hs[ti][hid] = gelu_f(hv);
        }
        __syncthreads();
        const float* wq = w2 + (size_t)e * 32 * 512;
        for (int q = 0; q < nb; q++) {
            float s0 = 0.f, s1 = 0.f;
            #pragma unroll
            for (int j = 0; j < 32; j++) {
                float h = hs[q][j];
                s0 += h * wq[j * 512 + tid];
                s1 += h * wq[j * 512 + tid + 256];
            }
            int a = g_elist[e * 64 + base + q];
            g_eout[(size_t)a * 512 + tid]       = s0;
            g_eout[(size_t)a * 512 + tid + 256] = s1;
        }
        __syncthreads();
    }
}

// ---------------- combine ----------------
__global__ void combine_k(float* __restrict__ o1, float* __restrict__ o2) {
    int i = blockIdx.x * 256 + threadIdx.x;
    int t = i >> 9;
    float g1 = g_g1[t], g2 = g_g2[t];
    float v = 0.f;
    if (g1 != 0.f) v += g1 * g_eout[(size_t)(t * 2) * 512 + (i & 511)];
    if (g2 != 0.f) v += g2 * g_eout[(size_t)(t * 2 + 1) * 512 + (i & 511)];
    o1[i] = v;
    o2[i] = v;
}

// ---------------- max pool ----------------
__global__ void pool_k(const float* __restrict__ y0, float* __restrict__ out) {
    int i = blockIdx.x * 256 + threadIdx.x;
    int j = i & 255, bc = i >> 8;
    const float* r = y0 + bc * 512;
    int l = 2 * j;
    float m = r[l];
    if (l > 0) m = fmaxf(m, r[l - 1]);
    m = fmaxf(m, r[l + 1]);
    out[i] = m;
}

// ---------------- launch ----------------
extern "C" void kernel_launch(void* const* d_in, const int* in_sizes, int n_in,
                              void* d_out, int out_size) {
    const float* x     = (const float*)d_in[0];
    const float* emb   = (const float*)d_in[1];
    const float* r1g1s = (const float*)d_in[2];
    const float* r1g1b = (const float*)d_in[3];
    const float* r1c1w = (const float*)d_in[4];
    const float* r1c1b = (const float*)d_in[5];
    const float* r1g2s = (const float*)d_in[6];
    const float* r1g2b = (const float*)d_in[7];
    const float* r1c2w = (const float*)d_in[8];
    const float* r1c2b = (const float*)d_in[9];
    const float* r2g1s = (const float*)d_in[10];
    const float* r2g1b = (const float*)d_in[11];
    const float* r2c1w = (const float*)d_in[12];
    const float* r2c1b = (const float*)d_in[13];
    const float* r2g2s = (const float*)d_in[14];
    const float* r2g2b = (const float*)d_in[15];
    const float* r2c2w = (const float*)d_in[16];
    const float* r2c2b = (const float*)d_in[17];
    const float* aw1   = (const float*)d_in[18];
    const float* ab1   = (const float*)d_in[19];
    const float* aw2   = (const float*)d_in[20];
    const float* ab2   = (const float*)d_in[21];
    const float* mwg   = (const float*)d_in[22];
    const float* mw1   = (const float*)d_in[23];
    const float* mw2   = (const float*)d_in[24];
    const float* ow    = (const float*)d_in[25];
    const float* ob    = (const float*)d_in[26];
    float* out = (float*)d_out;

    float *S1, *S2, *S3, *T;
    cudaGetSymbolAddress((void**)&S1, g_S1);
    cudaGetSymbolAddress((void**)&S2, g_S2);
    cudaGetSymbolAddress((void**)&S3, g_S3);
    cudaGetSymbolAddress((void**)&T,  g_T);

    cudaFuncSetAttribute(attn_k, cudaFuncAttributeMaxDynamicSharedMemorySize, 131072);
    cudaFuncSetAttribute(qkv_k,  cudaFuncAttributeMaxDynamicSharedMemorySize, 24 * QKV_GSTR * 4);

    // res_block 1 (x+emb fused into gn + conv residual)
    gn_k<<<256, 512>>>(x, emb, r1g1s, r1g1b, S2);
    conv16_k<<<dim3(2, 16, 8), 256>>>(S2, r1c1w, r1c1b, nullptr, nullptr, S3, 256);
    gn_k<<<256, 512>>>(S3, nullptr, r1g2s, r1g2b, S2);
    conv16_k<<<dim3(2, 16, 8), 256>>>(S2, r1c2w, r1c2b, x, emb, S3, 256);

    // attention
    qkv_k<<<dim3(8, 16), 384, 24 * QKV_GSTR * 4>>>(S3, aw1, ab1, T);
    attn_k<<<dim3(8, 8, 4), 128, 131072>>>(T, S2);
    oproj_k<<<dim3(8, 16), 128>>>(S2, aw2, ab2, emb, S1);

    // res_block 2
    gn_k<<<256, 512>>>(S1, nullptr, r2g1s, r2g1b, S2);
    conv16_k<<<dim3(2, 16, 8), 256>>>(S2, r2c1w, r2c1b, nullptr, nullptr, S3, 256);
    gn_k<<<256, 512>>>(S3, nullptr, r2g2s, r2g2b, S2);
    conv16_k<<<dim3(2, 16, 8), 256>>>(S2, r2c2w, r2c2b, S1, nullptr, S3, 256);

    // MoE
    zero_k<<<36, 256>>>();
    gate_k<<<512, 256>>>(S3, mwg);
    cap_k<<<8, 256>>>();
    loss_k<<<1, 256>>>(out + 2 * 1048576);
    scatter_k<<<8, 256>>>();
    expert_k<<<1024, 256>>>(S3, mw1, mw2);
    combine_k<<<4096, 256>>>(S2, out + 1048576);

    // output conv + maxpool
    conv16_k<<<dim3(2, 32, 8), 256>>>(S2, ow, ob, nullptr, nullptr, T, 512);
    pool_k<<<4096, 256>>>(T, out);
}

// round 11
// speedup vs baseline: 1.0014x; 1.0014x over previous
#include <cuda_runtime.h>
#include <math.h>

#define Bb 8
#define Cc 256
#define Ll 512
#define NG 32
#define NH 8
#define Ee 1024
#define NTOK (Bb*Cc)

typedef unsigned long long u64;

// ---------------- f32x2 helpers ----------------
__device__ __forceinline__ u64 fma2(u64 a, u64 b, u64 c) {
    u64 d; asm("fma.rn.f32x2 %0, %1, %2, %3;" : "=l"(d) : "l"(a), "l"(b), "l"(c)); return d;
}
__device__ __forceinline__ u64 mul2(u64 a, u64 b) {
    u64 d; asm("mul.rn.f32x2 %0, %1, %2;" : "=l"(d) : "l"(a), "l"(b)); return d;
}
__device__ __forceinline__ u64 add2(u64 a, u64 b) {
    u64 d; asm("add.rn.f32x2 %0, %1, %2;" : "=l"(d) : "l"(a), "l"(b)); return d;
}
__device__ __forceinline__ u64 pk2(float x, float y) {
    u64 d; asm("mov.b64 %0, {%1, %2};" : "=l"(d) : "r"(__float_as_uint(x)), "r"(__float_as_uint(y))); return d;
}
__device__ __forceinline__ float2 unpk2(u64 a) {
    unsigned int x, y; asm("mov.b64 {%0, %1}, %2;" : "=r"(x), "=r"(y) : "l"(a));
    return make_float2(__uint_as_float(x), __uint_as_float(y));
}

// ---------------- scratch ----------------
__device__ float g_S1[Bb*Cc*Ll];
__device__ float g_S2[Bb*Cc*Ll];
__device__ float g_S3[Bb*Cc*Ll];
__device__ float g_T [Bb*Ll*768];          // Q | K | V each 1048576 floats; also final conv out
__device__ float g_P [2*Bb*512*Ll];        // conv ci-split partials (max Cout=512)
__device__ float g_rawsum[Bb*Ee];
__device__ int   g_cnt1[Bb*Ee];
__device__ int   g_idx1[NTOK];
__device__ int   g_idx2[NTOK];
__device__ float g_g1[NTOK];
__device__ float g_g2[NTOK];
__device__ int   g_ecnt[Ee];
__device__ int   g_elist[Ee*64];
__device__ float g_eout[NTOK*2*512];

__device__ __forceinline__ float gelu_f(float x) {
    return 0.5f * x * (1.0f + erff(x * 0.70710678118654752f));
}

// ---------------- fused groupnorm (+opt add) + gelu: one CTA per (b,g) ----------------
__global__ __launch_bounds__(512) void gn_k(const float* __restrict__ in, const float* __restrict__ in2,
                                            const float* __restrict__ sc, const float* __restrict__ bi,
                                            float* __restrict__ out) {
    __shared__ float4 buf[1024];
    __shared__ float rs[16], rq[16];
    int bg = blockIdx.x, tid = threadIdx.x;
    const float4* p  = (const float4*)(in + bg * 4096);
    const float4* p2 = in2 ? (const float4*)(in2 + bg * 4096) : nullptr;
    float s = 0.f, q = 0.f;
    #pragma unroll
    for (int r = 0; r < 2; r++) {
        int i = tid + r * 512;
        float4 v = p[i];
        if (p2) {
            float4 w = p2[i];
            v.x += w.x; v.y += w.y; v.z += w.z; v.w += w.w;
        }
        buf[i] = v;
        s += v.x + v.y + v.z + v.w;
        q += v.x*v.x + v.y*v.y + v.z*v.z + v.w*v.w;
    }
    #pragma unroll
    for (int o = 16; o > 0; o >>= 1) {
        s += __shfl_down_sync(0xffffffffu, s, o);
        q += __shfl_down_sync(0xffffffffu, q, o);
    }
    if ((tid & 31) == 0) { rs[tid >> 5] = s; rq[tid >> 5] = q; }
    __syncthreads();
    if (tid < 32) {
        float s2 = (tid < 16) ? rs[tid] : 0.f;
        float q2 = (tid < 16) ? rq[tid] : 0.f;
        #pragma unroll
        for (int o = 8; o > 0; o >>= 1) {
            s2 += __shfl_down_sync(0xffffffffu, s2, o);
            q2 += __shfl_down_sync(0xffffffffu, q2, o);
        }
        if (tid == 0) {
            float mean = s2 * (1.f / 4096.f);
            float var  = q2 * (1.f / 4096.f) - mean * mean;
            rs[0] = mean;
            rq[0] = rsqrtf(var + 1e-5f);
        }
    }
    __syncthreads();
    float mean = rs[0], rstd = rq[0];
    float4* op = (float4*)(out + bg * 4096);
    int cbase = (bg & 31) * 8;
    #pragma unroll
    for (int r = 0; r < 2; r++) {
        int i = tid + r * 512;
        int c = cbase + (i >> 7);
        float a = rstd * sc[c];
        float b = bi[c] - mean * a;
        float4 v = buf[i];
        v.x = gelu_f(v.x * a + b);
        v.y = gelu_f(v.y * a + b);
        v.z = gelu_f(v.z * a + b);
        v.w = gelu_f(v.w * a + b);
        op[i] = v;
    }
}

// ---------------- conv1d k=3 ci-split: 16 co, 128 ci-half, 128-l tile per CTA ----------------
// grid: (4 l-tiles * 2 ci-halves, Cout/16, 8 batch), 128 threads
__global__ __launch_bounds__(128) void conv16s_k(
    const float* __restrict__ in, const float* __restrict__ w,
    float* __restrict__ P, int Cout) {
    __shared__ float4 ws4[128 * 3 * 4];          // 16 co x 128 ci x 3 taps = 24KB
    float* wsf = (float*)ws4;
    int b = blockIdx.z, co0 = blockIdx.y * 16;
    int lt = blockIdx.x >> 1, ch = blockIdx.x & 1;
    int l = lt * 128 + threadIdx.x;
    int ci0 = ch << 7;
    // weights: wsf[(ciL*3+t)*16 + cl] = w[(co0+cl)*768 + (ci0+ciL)*3 + t]
    for (int i = threadIdx.x; i < 16 * 384; i += 128) {
        int r = i >> 4, cl = i & 15;
        wsf[i] = w[(co0 + cl) * 768 + ci0 * 3 + r];
    }
    __syncthreads();
    u64 acc[8];
    #pragma unroll
    for (int p = 0; p < 8; p++) acc[p] = 0ull;
    const float* ip = in + (b * 256 + ci0) * 512;
    const ulonglong2* wd2 = (const ulonglong2*)wsf;
    #pragma unroll 2
    for (int ci = 0; ci < 128; ci++) {
        const float* row = ip + ci * 512;
        float xm = (l > 0)   ? __ldg(row + l - 1) : 0.f;
        float x0 = __ldg(row + l);
        float xp = (l < 511) ? __ldg(row + l + 1) : 0.f;
        u64 um = pk2(xm, xm), u0 = pk2(x0, x0), up = pk2(xp, xp);
        const ulonglong2* wp = wd2 + ci * 12;
        #pragma unroll
        for (int j = 0; j < 4; j++) {
            ulonglong2 w0 = wp[j];
            ulonglong2 w1 = wp[4 + j];
            ulonglong2 w2 = wp[8 + j];
            acc[2*j]   = fma2(um, w0.x, acc[2*j]);
            acc[2*j]   = fma2(u0, w1.x, acc[2*j]);
            acc[2*j]   = fma2(up, w2.x, acc[2*j]);
            acc[2*j+1] = fma2(um, w0.y, acc[2*j+1]);
            acc[2*j+1] = fma2(u0, w1.y, acc[2*j+1]);
            acc[2*j+1] = fma2(up, w2.y, acc[2*j+1]);
        }
    }
    float* op = P + (size_t)ch * (Bb * Cout * 512) + (b * Cout + co0) * 512 + l;
    #pragma unroll
    for (int p = 0; p < 8; p++) {
        float2 v = unpk2(acc[p]);
        op[(2*p)     * 512] = v.x;
        op[(2*p + 1) * 512] = v.y;
    }
}

// ---------------- combine conv partials + bias + residual(s) ----------------
__global__ __launch_bounds__(256) void ccomb_k(
    const float* __restrict__ bias,
    const float* __restrict__ residA, const float* __restrict__ residB,
    float* __restrict__ out, int Cout) {
    int i = blockIdx.x * 256 + threadIdx.x;        // float4 index over Bb*Cout*128
    int co = (i >> 7) & (Cout - 1);
    const float4* P0 = (const float4*)g_P;
    const float4* P1 = P0 + Bb * Cout * 128;
    float4 a = P0[i];
    float4 c = P1[i];
    float bb = bias[co];
    a.x += c.x + bb; a.y += c.y + bb; a.z += c.z + bb; a.w += c.w + bb;
    if (residA) {
        float4 r = ((const float4*)residA)[i];
        a.x += r.x; a.y += r.y; a.z += r.z; a.w += r.w;
        if (residB) {
            float4 r2 = ((const float4*)residB)[i];
            a.x += r2.x; a.y += r2.y; a.z += r2.z; a.w += r2.w;
        }
    }
    ((float4*)out)[i] = a;
}

// ---------------- QKV: computes tile, stages through smem, writes Q/K/V[b,h,l,32] ----------------
#define QKV_GSTR 545
__global__ __launch_bounds__(384) void qkv_k(const float* __restrict__ x, const float* __restrict__ w1,
                                             const float* __restrict__ b1, float* __restrict__ qkv) {
    extern __shared__ float sm[];
    int b = blockIdx.x, l0 = blockIdx.y * 32;
    for (int i = threadIdx.x; i < 256 * 32; i += 384) {
        int c = i >> 5, j = i & 31;
        sm[i] = x[(b * 256 + c) * 512 + l0 + j];
    }
    __syncthreads();
    int f = threadIdx.x;
    u64 A[16], B[16];
    {
        u64 ba = pk2(b1[f], b1[f]);
        u64 bb = pk2(b1[f + 384], b1[f + 384]);
        #pragma unroll
        for (int k = 0; k < 16; k++) { A[k] = ba; B[k] = bb; }
    }
    for (int c = 0; c < 256; c++) {
        float wa = w1[c * 768 + f];
        float wb = w1[c * 768 + f + 384];
        u64 ua = pk2(wa, wa), ub = pk2(wb, wb);
        const u64* xr = (const u64*)(sm + c * 32);
        #pragma unroll
        for (int k = 0; k < 16; k++) {
            u64 xv = xr[k];
            A[k] = fma2(xv, ua, A[k]);
            B[k] = fma2(xv, ub, B[k]);
        }
    }
    __syncthreads();
    int dd = f / 24, g = f - dd * 24;
    #pragma unroll
    for (int half = 0; half < 2; half++) {
        u64* R = half ? B : A;
        #pragma unroll
        for (int k = 0; k < 16; k++) {
            float2 v = unpk2(R[k]);
            sm[g * QKV_GSTR + (2*k)     * 17 + dd] = v.x;
            sm[g * QKV_GSTR + (2*k + 1) * 17 + dd] = v.y;
        }
        __syncthreads();
        #pragma unroll
        for (int rep = 0; rep < 2; rep++) {
            int j = threadIdx.x + rep * 384;
            int gg = j >> 5, l = j & 31;
            int h = gg / 3, kk = gg - h * 3;
            const float* srow = sm + gg * QKV_GSTR + l * 17;
            float4* dp = (float4*)(qkv + kk * 1048576 + (((b * 8) + h) * 512 + l0 + l) * 32 + half * 16);
            #pragma unroll
            for (int q4 = 0; q4 < 4; q4++)
                dp[q4] = make_float4(srow[q4*4], srow[q4*4+1], srow[q4*4+2], srow[q4*4+3]);
        }
        __syncthreads();
    }
}

// ---------------- attention: grid (b, h, 4 q-tiles), 128 threads ----------------
__global__ __launch_bounds__(128) void attn_k(const float* __restrict__ qkv, float* __restrict__ O) {
    extern __shared__ float sm[];
    float* Kf = sm;
    float* Vf = sm + 512 * 32;
    int b = blockIdx.x, h = blockIdx.y, qt = blockIdx.z, tid = threadIdx.x;
    int bh = b * 8 + h;
    {
        const float4* Ks = (const float4*)(qkv + 1048576 + bh * 16384);
        const float4* Vs = (const float4*)(qkv + 2097152 + bh * 16384);
        float4* Kd = (float4*)Kf;
        float4* Vd = (float4*)Vf;
        for (int i = tid; i < 4096; i += 128) {
            Kd[i] = Ks[i];
            Vd[i] = Vs[i];
        }
    }
    __syncthreads();
    int q = qt * 128 + tid;
    const float scale = 0.17677669529663687f;
    u64 q2[16];
    {
        const float* qb = qkv + (bh * 512 + q) * 32;
        #pragma unroll
        for (int i = 0; i < 16; i++)
            q2[i] = pk2(qb[2*i] * scale, qb[2*i + 1] * scale);
    }
    const u64* K2 = (const u64*)Kf;
    const u64* V2 = (const u64*)Vf;
    float m = -1e30f, s = 0.f;
    u64 acc2[16];
    #pragma unroll
    for (int i = 0; i < 16; i++) acc2[i] = 0ull;
    #pragma unroll 2
    for (int k = 0; k < 512; k++) {
        const u64* kr = K2 + k * 16;
        u64 d0 = mul2(q2[0], kr[0]);
        u64 d1 = mul2(q2[1], kr[1]);
        u64 d2 = mul2(q2[2], kr[2]);
        u64 d3 = mul2(q2[3], kr[3]);
        #pragma unroll
        for (int i = 4; i < 16; i += 4) {
            d0 = fma2(q2[i],     kr[i],     d0);
            d1 = fma2(q2[i + 1], kr[i + 1], d1);
            d2 = fma2(q2[i + 2], kr[i + 2], d2);
            d3 = fma2(q2[i + 3], kr[i + 3], d3);
        }
        d0 = add2(d0, d1);
        d2 = add2(d2, d3);
        d0 = add2(d0, d2);
        float2 dd = unpk2(d0);
        float dot = dd.x + dd.y;
        const u64* vr = V2 + k * 16;
        if (dot <= m) {
            float p = __expf(dot - m);
            s += p;
            u64 p2 = pk2(p, p);
            #pragma unroll
            for (int i = 0; i < 16; i++) acc2[i] = fma2(p2, vr[i], acc2[i]);
        } else {
            float corr = __expf(m - dot);
            m = dot;
            s = s * corr + 1.f;
            u64 c2 = pk2(corr, corr);
            #pragma unroll
            for (int i = 0; i < 16; i++) acc2[i] = fma2(acc2[i], c2, vr[i]);
        }
    }
    float inv = 1.f / s;
    float* op = O + (b * 512 + q) * 256 + h;
    #pragma unroll
    for (int i = 0; i < 16; i++) {
        float2 v = unpk2(acc2[i]);
        op[(2*i)     * 8] = v.x * inv;
        op[(2*i + 1) * 8] = v.y * inv;
    }
}

// ---------------- out projection ----------------
__global__ __launch_bounds__(128) void oproj_k(const float* __restrict__ O, const float* __restrict__ w2,
                                               const float* __restrict__ b2, const float* __restrict__ emb,
                                               float* __restrict__ out) {
    __shared__ float os[256][36];
    int b = blockIdx.x, l0 = blockIdx.y * 32;
    for (int i = threadIdx.x; i < 32 * 256; i += 128) {
        int c = i & 255, j = i >> 8;
        os[c][j] = O[(b * 512 + l0 + j) * 256 + c];
    }
    __syncthreads();
    int co = threadIdx.x;
    u64 A[16], B[16];
    {
        u64 ba = pk2(b2[co], b2[co]);
        u64 bb = pk2(b2[co + 128], b2[co + 128]);
        #pragma unroll
        for (int k = 0; k < 16; k++) { A[k] = ba; B[k] = bb; }
    }
    for (int c = 0; c < 256; c++) {
        float wa = w2[c * 256 + co];
        float wb = w2[c * 256 + co + 128];
        u64 ua = pk2(wa, wa), ub = pk2(wb, wb);
        const u64* xr = (const u64*)os[c];
        #pragma unroll
        for (int k = 0; k < 16; k++) {
            u64 xv = xr[k];
            A[k] = fma2(xv, ua, A[k]);
            B[k] = fma2(xv, ub, B[k]);
        }
    }
    #pragma unroll
    for (int k = 0; k < 16; k++) {
        float2 va = unpk2(A[k]);
        float2 vb = unpk2(B[k]);
        int oi  = (b * 256 + co) * 512 + l0 + 2*k;
        int oi2 = (b * 256 + co + 128) * 512 + l0 + 2*k;
        out[oi]      = va.x + emb[oi];
        out[oi + 1]  = va.y + emb[oi + 1];
        out[oi2]     = vb.x + emb[oi2];
        out[oi2 + 1] = vb.y + emb[oi2 + 1];
    }
}

// ---------------- zero rawsum + ecnt ----------------
__global__ void zero_k() {
    int i = blockIdx.x * 256 + threadIdx.x;
    if (i < Bb * Ee) g_rawsum[i] = 0.f;
    else if (i < Bb * Ee + Ee) g_ecnt[i - Bb * Ee] = 0;
}

// ---------------- gating: 4 tokens per block ----------------
__global__ __launch_bounds__(256) void gate_k(const float* __restrict__ X, const float* __restrict__ wg) {
    __shared__ float xv[4][512];
    __shared__ float red[256];
    __shared__ int redi[256];
    int t0 = blockIdx.x * 4, tid = threadIdx.x, b = t0 >> 8;
    for (int i = tid; i < 4 * 512; i += 256) {
        int tok = i >> 9, d = i & 511;
        xv[tok][d] = X[(t0 + tok) * 512 + d];
    }
    __syncthreads();
    int e0 = tid * 4;
    float acc[4][4];
    #pragma unroll
    for (int tk = 0; tk < 4; tk++)
        #pragma unroll
        for (int j = 0; j < 4; j++) acc[tk][j] = 0.f;
    for (int d = 0; d < 512; d++) {
        float4 w = *(const float4*)(wg + d * 1024 + e0);
        #pragma unroll
        for (int tk = 0; tk < 4; tk++) {
            float xd = xv[tk][d];
            acc[tk][0] += xd * w.x; acc[tk][1] += xd * w.y;
            acc[tk][2] += xd * w.z; acc[tk][3] += xd * w.w;
        }
    }
    float rs[4] = {0.f, 0.f, 0.f, 0.f};
    for (int tk = 0; tk < 4; tk++) {
        int t = t0 + tk;
        float l0 = acc[tk][0], l1 = acc[tk][1], l2 = acc[tk][2], l3 = acc[tk][3];
        float lm = fmaxf(fmaxf(l0, l1), fmaxf(l2, l3));
        red[tid] = lm; __syncthreads();
        for (int s = 128; s > 0; s >>= 1) { if (tid < s) red[tid] = fmaxf(red[tid], red[tid + s]); __syncthreads(); }
        float gmax = red[0]; __syncthreads();
        float e_0 = __expf(l0 - gmax), e_1 = __expf(l1 - gmax), e_2 = __expf(l2 - gmax), e_3 = __expf(l3 - gmax);
        red[tid] = e_0 + e_1 + e_2 + e_3; __syncthreads();
        for (int s = 128; s > 0; s >>= 1) { if (tid < s) red[tid] += red[tid + s]; __syncthreads(); }
        float inv = 1.f / red[0]; __syncthreads();
        rs[0] += e_0 * inv; rs[1] += e_1 * inv; rs[2] += e_2 * inv; rs[3] += e_3 * inv;
        float bv = l0; int bi = e0;
        if (l1 > bv) { bv = l1; bi = e0 + 1; }
        if (l2 > bv) { bv = l2; bi = e0 + 2; }
        if (l3 > bv) { bv = l3; bi = e0 + 3; }
        red[tid] = bv; redi[tid] = bi; __syncthreads();
        for (int s = 128; s > 0; s >>= 1) {
            if (tid < s) {
                float ov = red[tid + s]; int oi = redi[tid + s];
                if (ov > red[tid] || (ov == red[tid] && oi < redi[tid])) { red[tid] = ov; redi[tid] = oi; }
            }
            __syncthreads();
        }
        float v1 = red[0]; int i1 = redi[0]; __syncthreads();
        float m0 = l0, m1 = l1, m2 = l2, m3 = l3;
        if      (i1 == e0)     m0 = -3e38f;
        else if (i1 == e0 + 1) m1 = -3e38f;
        else if (i1 == e0 + 2) m2 = -3e38f;
        else if (i1 == e0 + 3) m3 = -3e38f;
        bv = m0; bi = e0;
        if (m1 > bv) { bv = m1; bi = e0 + 1; }
        if (m2 > bv) { bv = m2; bi = e0 + 2; }
        if (m3 > bv) { bv = m3; bi = e0 + 3; }
        red[tid] = bv; redi[tid] = bi; __syncthreads();
        for (int s = 128; s > 0; s >>= 1) {
            if (tid < s) {
                float ov = red[tid + s]; int oi = redi[tid + s];
                if (ov > red[tid] || (ov == red[tid] && oi < redi[tid])) { red[tid] = ov; redi[tid] = oi; }
            }
            __syncthreads();
        }
        if (tid == 0) {
            float v2 = red[0]; int i2 = redi[0];
            float ga = __expf(v1 - gmax) * inv;
            float gb = __expf(v2 - gmax) * inv;
            float den = ga + gb + 1e-9f;
            g_idx1[t] = i1; g_idx2[t] = i2;
            g_g1[t] = ga / den; g_g2[t] = gb / den;
        }
        __syncthreads();
    }
    #pragma unroll
    for (int j = 0; j < 4; j++)
        if (rs[j] != 0.f) atomicAdd(&g_rawsum[b * 1024 + e0 + j], rs[j]);
}

// ---------------- capacity walk ----------------
__global__ void cap_k() {
    __shared__ int c1[1024], c2[1024];
    int b = blockIdx.x;
    for (int i = threadIdx.x; i < 1024; i += 256) { c1[i] = 0; c2[i] = 0; }
    __syncthreads();
    if (threadIdx.x == 0) {
        for (int n = 0; n < 256; n++) {
            int t = b * 256 + n; int e = g_idx1[t];
            if (c1[e] >= 4) g_g1[t] = 0.f;
            c1[e]++;
        }
        for (int n = 0; n < 256; n++) {
            int t = b * 256 + n; int e = g_idx2[t];
            int p = c2[e] + min(c1[e], 4);
            if (p >= 4) g_g2[t] = 0.f;
            c2[e]++;
        }
    }
    __syncthreads();
    for (int i = threadIdx.x; i < 1024; i += 256) g_cnt1[b * 1024 + i] = c1[i];
}

// ---------------- aux loss ----------------
__global__ void loss_k(float* __restrict__ aux) {
    __shared__ float red[256];
    float s = 0.f;
    for (int i = threadIdx.x; i < Bb * Ee; i += 256) s += g_rawsum[i] * (float)g_cnt1[i];
    red[threadIdx.x] = s; __syncthreads();
    for (int st = 128; st > 0; st >>= 1) { if (threadIdx.x < st) red[threadIdx.x] += red[threadIdx.x + st]; __syncthreads(); }
    if (threadIdx.x == 0) *aux = red[0] * (0.01f * (float)Ee / ((float)Bb * 256.f * 256.f));
}

// ---------------- scatter tokens to expert lists ----------------
__global__ void scatter_k() {
    int t = blockIdx.x * 256 + threadIdx.x;
    if (t >= NTOK) return;
    if (g_g1[t] != 0.f) {
        int e = g_idx1[t];
        int p = atomicAdd(&g_ecnt[e], 1);
        g_elist[e * 64 + p] = t * 2;
    }
    if (g_g2[t] != 0.f) {
        int e = g_idx2[t];
        int p = atomicAdd(&g_ecnt[e], 1);
        g_elist[e * 64 + p] = t * 2 + 1;
    }
}

// ---------------- expert compute: one block per expert ----------------
__global__ __launch_bounds__(256) void expert_k(const float* __restrict__ X, const float* __restrict__ w1,
                                                const float* __restrict__ w2) {
    int e = blockIdx.x;
    int nt = g_ecnt[e];
    if (nt == 0) return;
    __shared__ float xs[8][512];
    __shared__ float hs[8][32];
    int tid = threadIdx.x;
    for (int base = 0; base < nt; base += 8) {
        int nb = min(8, nt - base);
        for (int i = tid; i < nb * 512; i += 256) {
            int ti = i >> 9, d = i & 511;
            int a = g_elist[e * 64 + base + ti];
            xs[ti][d] = X[(a >> 1) * 512 + d];
        }
        __syncthreads();
        int ti = tid >> 5, hid = tid & 31;
        if (ti < nb) {
            float hv = 0.f;
            const float* wp = w1 + (size_t)e * 512 * 32 + hid;
            const float* xr = xs[ti];
            #pragma unroll 8
            for (int d = 0; d < 512; d++) hv += xr[d] * wp[d * 32];
            hs[ti][hid] = gelu_f(hv);
        }
        __syncthreads();
        const float* wq = w2 + (size_t)e * 32 * 512;
        for (int q = 0; q < nb; q++) {
            float s0 = 0.f, s1 = 0.f;
            #pragma unroll
            for (int j = 0; j < 32; j++) {
                float h = hs[q][j];
                s0 += h * wq[j * 512 + tid];
                s1 += h * wq[j * 512 + tid + 256];
            }
            int a = g_elist[e * 64 + base + q];
            g_eout[(size_t)a * 512 + tid]       = s0;
            g_eout[(size_t)a * 512 + tid + 256] = s1;
        }
        __syncthreads();
    }
}

// ---------------- combine MoE ----------------
__global__ void combine_k(float* __restrict__ o1, float* __restrict__ o2) {
    int i = blockIdx.x * 256 + threadIdx.x;
    int t = i >> 9;
    float g1 = g_g1[t], g2 = g_g2[t];
    float v = 0.f;
    if (g1 != 0.f) v += g1 * g_eout[(size_t)(t * 2) * 512 + (i & 511)];
    if (g2 != 0.f) v += g2 * g_eout[(size_t)(t * 2 + 1) * 512 + (i & 511)];
    o1[i] = v;
    o2[i] = v;
}

// ---------------- max pool ----------------
__global__ void pool_k(const float* __restrict__ y0, float* __restrict__ out) {
    int i = blockIdx.x * 256 + threadIdx.x;
    int j = i & 255, bc = i >> 8;
    const float* r = y0 + bc * 512;
    int l = 2 * j;
    float m = r[l];
    if (l > 0) m = fmaxf(m, r[l - 1]);
    m = fmaxf(m, r[l + 1]);
    out[i] = m;
}

// ---------------- launch ----------------
extern "C" void kernel_launch(void* const* d_in, const int* in_sizes, int n_in,
                              void* d_out, int out_size) {
    const float* x     = (const float*)d_in[0];
    const float* emb   = (const float*)d_in[1];
    const float* r1g1s = (const float*)d_in[2];
    const float* r1g1b = (const float*)d_in[3];
    const float* r1c1w = (const float*)d_in[4];
    const float* r1c1b = (const float*)d_in[5];
    const float* r1g2s = (const float*)d_in[6];
    const float* r1g2b = (const float*)d_in[7];
    const float* r1c2w = (const float*)d_in[8];
    const float* r1c2b = (const float*)d_in[9];
    const float* r2g1s = (const float*)d_in[10];
    const float* r2g1b = (const float*)d_in[11];
    const float* r2c1w = (const float*)d_in[12];
    const float* r2c1b = (const float*)d_in[13];
    const float* r2g2s = (const float*)d_in[14];
    const float* r2g2b = (const float*)d_in[15];
    const float* r2c2w = (const float*)d_in[16];
    const float* r2c2b = (const float*)d_in[17];
    const float* aw1   = (const float*)d_in[18];
    const float* ab1   = (const float*)d_in[19];
    const float* aw2   = (const float*)d_in[20];
    const float* ab2   = (const float*)d_in[21];
    const float* mwg   = (const float*)d_in[22];
    const float* mw1   = (const float*)d_in[23];
    const float* mw2   = (const float*)d_in[24];
    const float* ow    = (const float*)d_in[25];
    const float* ob    = (const float*)d_in[26];
    float* out = (float*)d_out;

    float *S1, *S2, *S3, *T, *P;
    cudaGetSymbolAddress((void**)&S1, g_S1);
    cudaGetSymbolAddress((void**)&S2, g_S2);
    cudaGetSymbolAddress((void**)&S3, g_S3);
    cudaGetSymbolAddress((void**)&T,  g_T);
    cudaGetSymbolAddress((void**)&P,  g_P);

    cudaFuncSetAttribute(attn_k, cudaFuncAttributeMaxDynamicSharedMemorySize, 131072);
    cudaFuncSetAttribute(qkv_k,  cudaFuncAttributeMaxDynamicSharedMemorySize, 24 * QKV_GSTR * 4);

    // res_block 1
    gn_k<<<256, 512>>>(x, emb, r1g1s, r1g1b, S2);
    conv16s_k<<<dim3(8, 16, 8), 128>>>(S2, r1c1w, P, 256);
    ccomb_k<<<1024, 256>>>(r1c1b, nullptr, nullptr, S3, 256);
    gn_k<<<256, 512>>>(S3, nullptr, r1g2s, r1g2b, S2);
    conv16s_k<<<dim3(8, 16, 8), 128>>>(S2, r1c2w, P, 256);
    ccomb_k<<<1024, 256>>>(r1c2b, x, emb, S3, 256);

    // attention
    qkv_k<<<dim3(8, 16), 384, 24 * QKV_GSTR * 4>>>(S3, aw1, ab1, T);
    attn_k<<<dim3(8, 8, 4), 128, 131072>>>(T, S2);
    oproj_k<<<dim3(8, 16), 128>>>(S2, aw2, ab2, emb, S1);

    // res_block 2
    gn_k<<<256, 512>>>(S1, nullptr, r2g1s, r2g1b, S2);
    conv16s_k<<<dim3(8, 16, 8), 128>>>(S2, r2c1w, P, 256);
    ccomb_k<<<1024, 256>>>(r2c1b, nullptr, nullptr, S3, 256);
    gn_k<<<256, 512>>>(S3, nullptr, r2g2s, r2g2b, S2);
    conv16s_k<<<dim3(8, 16, 8), 128>>>(S2, r2c2w, P, 256);
    ccomb_k<<<1024, 256>>>(r2c2b, S1, nullptr, S3, 256);

    // MoE
    zero_k<<<36, 256>>>();
    gate_k<<<512, 256>>>(S3, mwg);
    cap_k<<<8, 256>>>();
    loss_k<<<1, 256>>>(out + 2 * 1048576);
    scatter_k<<<8, 256>>>();
    expert_k<<<1024, 256>>>(S3, mw1, mw2);
    combine_k<<<4096, 256>>>(S2, out + 1048576);

    // output conv + maxpool
    conv16s_k<<<dim3(8, 32, 8), 128>>>(S2, ow, P, 512);
    ccomb_k<<<2048, 256>>>(ob, nullptr, nullptr, T, 512);
    pool_k<<<4096, 256>>>(T, out);
}

// round 12
// speedup vs baseline: 1.0153x; 1.0139x over previous
#include <cuda_runtime.h>
#include <math.h>

#define Bb 8
#define Cc 256
#define Ll 512
#define NG 32
#define NH 8
#define Ee 1024
#define NTOK (Bb*Cc)

typedef unsigned long long u64;

// ---------------- f32x2 helpers ----------------
__device__ __forceinline__ u64 fma2(u64 a, u64 b, u64 c) {
    u64 d; asm("fma.rn.f32x2 %0, %1, %2, %3;" : "=l"(d) : "l"(a), "l"(b), "l"(c)); return d;
}
__device__ __forceinline__ u64 mul2(u64 a, u64 b) {
    u64 d; asm("mul.rn.f32x2 %0, %1, %2;" : "=l"(d) : "l"(a), "l"(b)); return d;
}
__device__ __forceinline__ u64 add2(u64 a, u64 b) {
    u64 d; asm("add.rn.f32x2 %0, %1, %2;" : "=l"(d) : "l"(a), "l"(b)); return d;
}
__device__ __forceinline__ u64 pk2(float x, float y) {
    u64 d; asm("mov.b64 %0, {%1, %2};" : "=l"(d) : "r"(__float_as_uint(x)), "r"(__float_as_uint(y))); return d;
}
__device__ __forceinline__ float2 unpk2(u64 a) {
    unsigned int x, y; asm("mov.b64 {%0, %1}, %2;" : "=r"(x), "=r"(y) : "l"(a));
    return make_float2(__uint_as_float(x), __uint_as_float(y));
}

// ---------------- scratch ----------------
__device__ float g_S1[Bb*Cc*Ll];
__device__ float g_S2[Bb*Cc*Ll];
__device__ float g_S3[Bb*Cc*Ll];
__device__ float g_T [Bb*Ll*768];          // Q | K | V each 1048576 floats; also final conv out
__device__ float g_rawsum[Bb*Ee];
__device__ int   g_cnt1[Bb*Ee];
__device__ int   g_idx1[NTOK];
__device__ int   g_idx2[NTOK];
__device__ float g_g1[NTOK];
__device__ float g_g2[NTOK];
__device__ int   g_ecnt[Ee];
__device__ int   g_elist[Ee*64];
__device__ float g_eout[NTOK*2*512];

__device__ __forceinline__ float gelu_f(float x) {
    return 0.5f * x * (1.0f + erff(x * 0.70710678118654752f));
}

// ---------------- fused groupnorm (+opt add) + gelu: one CTA per (b,g) ----------------
__global__ __launch_bounds__(512) void gn_k(const float* __restrict__ in, const float* __restrict__ in2,
                                            const float* __restrict__ sc, const float* __restrict__ bi,
                                            float* __restrict__ out) {
    __shared__ float4 buf[1024];
    __shared__ float rs[16], rq[16];
    int bg = blockIdx.x, tid = threadIdx.x;
    const float4* p  = (const float4*)(in + bg * 4096);
    const float4* p2 = in2 ? (const float4*)(in2 + bg * 4096) : nullptr;
    float s = 0.f, q = 0.f;
    #pragma unroll
    for (int r = 0; r < 2; r++) {
        int i = tid + r * 512;
        float4 v = p[i];
        if (p2) {
            float4 w = p2[i];
            v.x += w.x; v.y += w.y; v.z += w.z; v.w += w.w;
        }
        buf[i] = v;
        s += v.x + v.y + v.z + v.w;
        q += v.x*v.x + v.y*v.y + v.z*v.z + v.w*v.w;
    }
    #pragma unroll
    for (int o = 16; o > 0; o >>= 1) {
        s += __shfl_down_sync(0xffffffffu, s, o);
        q += __shfl_down_sync(0xffffffffu, q, o);
    }
    if ((tid & 31) == 0) { rs[tid >> 5] = s; rq[tid >> 5] = q; }
    __syncthreads();
    if (tid < 32) {
        float s2 = (tid < 16) ? rs[tid] : 0.f;
        float q2 = (tid < 16) ? rq[tid] : 0.f;
        #pragma unroll
        for (int o = 8; o > 0; o >>= 1) {
            s2 += __shfl_down_sync(0xffffffffu, s2, o);
            q2 += __shfl_down_sync(0xffffffffu, q2, o);
        }
        if (tid == 0) {
            float mean = s2 * (1.f / 4096.f);
            float var  = q2 * (1.f / 4096.f) - mean * mean;
            rs[0] = mean;
            rq[0] = rsqrtf(var + 1e-5f);
        }
    }
    __syncthreads();
    float mean = rs[0], rstd = rq[0];
    float4* op = (float4*)(out + bg * 4096);
    int cbase = (bg & 31) * 8;
    #pragma unroll
    for (int r = 0; r < 2; r++) {
        int i = tid + r * 512;
        int c = cbase + (i >> 7);
        float a = rstd * sc[c];
        float b = bi[c] - mean * a;
        float4 v = buf[i];
        v.x = gelu_f(v.x * a + b);
        v.y = gelu_f(v.y * a + b);
        v.z = gelu_f(v.z * a + b);
        v.w = gelu_f(v.w * a + b);
        op[i] = v;
    }
}

// ---------------- conv1d k=3: 16 co per block, 2 l per thread, f32x2 math (R9 proven config) ----------------
__global__ __launch_bounds__(128) void conv16_k(
    const float* __restrict__ in, const float* __restrict__ w, const float* __restrict__ bias,
    const float* __restrict__ residA, const float* __restrict__ residB,
    float* __restrict__ out, int Cout) {
    __shared__ float4 ws4[256 * 3 * 4];
    float* wsf = (float*)ws4;
    int b = blockIdx.z, co0 = blockIdx.y * 16;
    int l  = blockIdx.x * 256 + threadIdx.x;
    int l2 = l + 128;
    for (int i = threadIdx.x; i < 16 * 768; i += 128) {
        int r = i >> 4, cl = i & 15;
        wsf[i] = w[(co0 + cl) * 768 + r];
    }
    __syncthreads();
    u64 accA[8], accB[8];
    #pragma unroll
    for (int p = 0; p < 8; p++) {
        u64 bb = pk2(bias[co0 + 2*p], bias[co0 + 2*p + 1]);
        accA[p] = bb; accB[p] = bb;
    }
    const float* ip = in + b * 256 * 512;
    const ulonglong2* wd2 = (const ulonglong2*)wsf;
    #pragma unroll 2
    for (int ci = 0; ci < 256; ci++) {
        const float* row = ip + ci * 512;
        float am = (l > 0)    ? __ldg(row + l - 1)  : 0.f;
        float a0 = __ldg(row + l);
        float ap = __ldg(row + l + 1);
        float bm = __ldg(row + l2 - 1);
        float b0 = __ldg(row + l2);
        float bp = (l2 < 511) ? __ldg(row + l2 + 1) : 0.f;
        u64 uam = pk2(am, am), ua0 = pk2(a0, a0), uap = pk2(ap, ap);
        u64 ubm = pk2(bm, bm), ub0 = pk2(b0, b0), ubp = pk2(bp, bp);
        const ulonglong2* wp = wd2 + ci * 12;
        #pragma unroll
        for (int j = 0; j < 4; j++) {
            ulonglong2 w0 = wp[j];
            ulonglong2 w1 = wp[4 + j];
            ulonglong2 w2 = wp[8 + j];
            accA[2*j]   = fma2(uam, w0.x, accA[2*j]);
            accA[2*j]   = fma2(ua0, w1.x, accA[2*j]);
            accA[2*j]   = fma2(uap, w2.x, accA[2*j]);
            accA[2*j+1] = fma2(uam, w0.y, accA[2*j+1]);
            accA[2*j+1] = fma2(ua0, w1.y, accA[2*j+1]);
            accA[2*j+1] = fma2(uap, w2.y, accA[2*j+1]);
            accB[2*j]   = fma2(ubm, w0.x, accB[2*j]);
            accB[2*j]   = fma2(ub0, w1.x, accB[2*j]);
            accB[2*j]   = fma2(ubp, w2.x, accB[2*j]);
            accB[2*j+1] = fma2(ubm, w0.y, accB[2*j+1]);
            accB[2*j+1] = fma2(ub0, w1.y, accB[2*j+1]);
            accB[2*j+1] = fma2(ubp, w2.y, accB[2*j+1]);
        }
    }
    int base = (b * Cout + co0) * 512;
    #pragma unroll
    for (int p = 0; p < 8; p++) {
        float2 va = unpk2(accA[p]);
        float2 vb = unpk2(accB[p]);
        int o0 = base + (2*p)     * 512;
        int o1 = base + (2*p + 1) * 512;
        float r0a = 0.f, r1a = 0.f, r0b = 0.f, r1b = 0.f;
        if (residA) {
            r0a = residA[o0 + l];  r1a = residA[o1 + l];
            r0b = residA[o0 + l2]; r1b = residA[o1 + l2];
            if (residB) {
                r0a += residB[o0 + l];  r1a += residB[o1 + l];
                r0b += residB[o0 + l2]; r1b += residB[o1 + l2];
            }
        }
        out[o0 + l]  = va.x + r0a;
        out[o1 + l]  = va.y + r1a;
        out[o0 + l2] = vb.x + r0b;
        out[o1 + l2] = vb.y + r1b;
    }
}

// ---------------- QKV: computes tile, stages through smem, writes Q/K/V[b,h,l,32] ----------------
#define QKV_GSTR 545
__global__ __launch_bounds__(384) void qkv_k(const float* __restrict__ x, const float* __restrict__ w1,
                                             const float* __restrict__ b1, float* __restrict__ qkv) {
    extern __shared__ float sm[];
    int b = blockIdx.x, l0 = blockIdx.y * 32;
    for (int i = threadIdx.x; i < 256 * 32; i += 384) {
        int c = i >> 5, j = i & 31;
        sm[i] = x[(b * 256 + c) * 512 + l0 + j];
    }
    __syncthreads();
    int f = threadIdx.x;
    u64 A[16], B[16];
    {
        u64 ba = pk2(b1[f], b1[f]);
        u64 bb = pk2(b1[f + 384], b1[f + 384]);
        #pragma unroll
        for (int k = 0; k < 16; k++) { A[k] = ba; B[k] = bb; }
    }
    for (int c = 0; c < 256; c++) {
        float wa = w1[c * 768 + f];
        float wb = w1[c * 768 + f + 384];
        u64 ua = pk2(wa, wa), ub = pk2(wb, wb);
        const u64* xr = (const u64*)(sm + c * 32);
        #pragma unroll
        for (int k = 0; k < 16; k++) {
            u64 xv = xr[k];
            A[k] = fma2(xv, ua, A[k]);
            B[k] = fma2(xv, ub, B[k]);
        }
    }
    __syncthreads();
    int dd = f / 24, g = f - dd * 24;
    #pragma unroll
    for (int half = 0; half < 2; half++) {
        u64* R = half ? B : A;
        #pragma unroll
        for (int k = 0; k < 16; k++) {
            float2 v = unpk2(R[k]);
            sm[g * QKV_GSTR + (2*k)     * 17 + dd] = v.x;
            sm[g * QKV_GSTR + (2*k + 1) * 17 + dd] = v.y;
        }
        __syncthreads();
        #pragma unroll
        for (int rep = 0; rep < 2; rep++) {
            int j = threadIdx.x + rep * 384;
            int gg = j >> 5, l = j & 31;
            int h = gg / 3, kk = gg - h * 3;
            const float* srow = sm + gg * QKV_GSTR + l * 17;
            float4* dp = (float4*)(qkv + kk * 1048576 + (((b * 8) + h) * 512 + l0 + l) * 32 + half * 16);
            #pragma unroll
            for (int q4 = 0; q4 < 4; q4++)
                dp[q4] = make_float4(srow[q4*4], srow[q4*4+1], srow[q4*4+2], srow[q4*4+3]);
        }
        __syncthreads();
    }
}

// ---------------- attention: grid (b, h, 4 q-tiles), 128 threads ----------------
__global__ __launch_bounds__(128) void attn_k(const float* __restrict__ qkv, float* __restrict__ O) {
    extern __shared__ float sm[];
    float* Kf = sm;
    float* Vf = sm + 512 * 32;
    int b = blockIdx.x, h = blockIdx.y, qt = blockIdx.z, tid = threadIdx.x;
    int bh = b * 8 + h;
    {
        const float4* Ks = (const float4*)(qkv + 1048576 + bh * 16384);
        const float4* Vs = (const float4*)(qkv + 2097152 + bh * 16384);
        float4* Kd = (float4*)Kf;
        float4* Vd = (float4*)Vf;
        for (int i = tid; i < 4096; i += 128) {
            Kd[i] = Ks[i];
            Vd[i] = Vs[i];
        }
    }
    __syncthreads();
    int q = qt * 128 + tid;
    const float scale = 0.17677669529663687f;
    u64 q2[16];
    {
        const float* qb = qkv + (bh * 512 + q) * 32;
        #pragma unroll
        for (int i = 0; i < 16; i++)
            q2[i] = pk2(qb[2*i] * scale, qb[2*i + 1] * scale);
    }
    const u64* K2 = (const u64*)Kf;
    const u64* V2 = (const u64*)Vf;
    float m = -1e30f, s = 0.f;
    u64 acc2[16];
    #pragma unroll
    for (int i = 0; i < 16; i++) acc2[i] = 0ull;
    #pragma unroll 2
    for (int k = 0; k < 512; k++) {
        const u64* kr = K2 + k * 16;
        u64 d0 = mul2(q2[0], kr[0]);
        u64 d1 = mul2(q2[1], kr[1]);
        u64 d2 = mul2(q2[2], kr[2]);
        u64 d3 = mul2(q2[3], kr[3]);
        #pragma unroll
        for (int i = 4; i < 16; i += 4) {
            d0 = fma2(q2[i],     kr[i],     d0);
            d1 = fma2(q2[i + 1], kr[i + 1], d1);
            d2 = fma2(q2[i + 2], kr[i + 2], d2);
            d3 = fma2(q2[i + 3], kr[i + 3], d3);
        }
        d0 = add2(d0, d1);
        d2 = add2(d2, d3);
        d0 = add2(d0, d2);
        float2 dd = unpk2(d0);
        float dot = dd.x + dd.y;
        const u64* vr = V2 + k * 16;
        if (dot <= m) {
            float p = __expf(dot - m);
            s += p;
            u64 p2 = pk2(p, p);
            #pragma unroll
            for (int i = 0; i < 16; i++) acc2[i] = fma2(p2, vr[i], acc2[i]);
        } else {
            float corr = __expf(m - dot);
            m = dot;
            s = s * corr + 1.f;
            u64 c2 = pk2(corr, corr);
            #pragma unroll
            for (int i = 0; i < 16; i++) acc2[i] = fma2(acc2[i], c2, vr[i]);
        }
    }
    float inv = 1.f / s;
    float* op = O + (b * 512 + q) * 256 + h;
    #pragma unroll
    for (int i = 0; i < 16; i++) {
        float2 v = unpk2(acc2[i]);
        op[(2*i)     * 8] = v.x * inv;
        op[(2*i + 1) * 8] = v.y * inv;
    }
}

// ---------------- out projection ----------------
__global__ __launch_bounds__(128) void oproj_k(const float* __restrict__ O, const float* __restrict__ w2,
                                               const float* __restrict__ b2, const float* __restrict__ emb,
                                               float* __restrict__ out) {
    __shared__ float os[256][36];
    int b = blockIdx.x, l0 = blockIdx.y * 32;
    for (int i = threadIdx.x; i < 32 * 256; i += 128) {
        int c = i & 255, j = i >> 8;
        os[c][j] = O[(b * 512 + l0 + j) * 256 + c];
    }
    __syncthreads();
    int co = threadIdx.x;
    u64 A[16], B[16];
    {
        u64 ba = pk2(b2[co], b2[co]);
        u64 bb = pk2(b2[co + 128], b2[co + 128]);
        #pragma unroll
        for (int k = 0; k < 16; k++) { A[k] = ba; B[k] = bb; }
    }
    for (int c = 0; c < 256; c++) {
        float wa = w2[c * 256 + co];
        float wb = w2[c * 256 + co + 128];
        u64 ua = pk2(wa, wa), ub = pk2(wb, wb);
        const u64* xr = (const u64*)os[c];
        #pragma unroll
        for (int k = 0; k < 16; k++) {
            u64 xv = xr[k];
            A[k] = fma2(xv, ua, A[k]);
            B[k] = fma2(xv, ub, B[k]);
        }
    }
    #pragma unroll
    for (int k = 0; k < 16; k++) {
        float2 va = unpk2(A[k]);
        float2 vb = unpk2(B[k]);
        int oi  = (b * 256 + co) * 512 + l0 + 2*k;
        int oi2 = (b * 256 + co + 128) * 512 + l0 + 2*k;
        out[oi]      = va.x + emb[oi];
        out[oi + 1]  = va.y + emb[oi + 1];
        out[oi2]     = vb.x + emb[oi2];
        out[oi2 + 1] = vb.y + emb[oi2 + 1];
    }
}

// ---------------- zero rawsum + ecnt ----------------
__global__ void zero_k() {
    int i = blockIdx.x * 256 + threadIdx.x;
    if (i < Bb * Ee) g_rawsum[i] = 0.f;
    else if (i < Bb * Ee + Ee) g_ecnt[i - Bb * Ee] = 0;
}

// ---------------- gating v2: 8 tokens per block, f32x2 over token pairs ----------------
__global__ __launch_bounds__(256) void gate_k(const float* __restrict__ X, const float* __restrict__ wg) {
    __shared__ float xs[512][10];                // [d][8 tokens + pad]; rows 40B -> 8B-aligned pairs
    __shared__ float red[256];
    __shared__ int redi[256];
    int t0 = blockIdx.x * 8, tid = threadIdx.x, b = t0 >> 8;
    for (int i = tid; i < 8 * 512; i += 256) {
        int tok = i >> 9, d = i & 511;
        xs[d][tok] = X[(t0 + tok) * 512 + d];
    }
    __syncthreads();
    int e0 = tid * 4;
    u64 acc[4][4];
    #pragma unroll
    for (int tp = 0; tp < 4; tp++)
        #pragma unroll
        for (int j = 0; j < 4; j++) acc[tp][j] = 0ull;
    const float4* wgp = (const float4*)(wg + e0);
    for (int d = 0; d < 512; d++) {
        float4 w = __ldg(wgp + d * 256);
        u64 w0 = pk2(w.x, w.x), w1 = pk2(w.y, w.y), w2 = pk2(w.z, w.z), w3 = pk2(w.w, w.w);
        const u64* xp = (const u64*)xs[d];
        #pragma unroll
        for (int tp = 0; tp < 4; tp++) {
            u64 xv = xp[tp];
            acc[tp][0] = fma2(xv, w0, acc[tp][0]);
            acc[tp][1] = fma2(xv, w1, acc[tp][1]);
            acc[tp][2] = fma2(xv, w2, acc[tp][2]);
            acc[tp][3] = fma2(xv, w3, acc[tp][3]);
        }
    }
    float rs[4] = {0.f, 0.f, 0.f, 0.f};
    #pragma unroll
    for (int tk = 0; tk < 8; tk++) {
        int t = t0 + tk;
        float2 a0 = unpk2(acc[tk >> 1][0]);
        float2 a1 = unpk2(acc[tk >> 1][1]);
        float2 a2 = unpk2(acc[tk >> 1][2]);
        float2 a3 = unpk2(acc[tk >> 1][3]);
        float l0 = (tk & 1) ? a0.y : a0.x;
        float l1 = (tk & 1) ? a1.y : a1.x;
        float l2 = (tk & 1) ? a2.y : a2.x;
        float l3 = (tk & 1) ? a3.y : a3.x;
        float lm = fmaxf(fmaxf(l0, l1), fmaxf(l2, l3));
        red[tid] = lm; __syncthreads();
        for (int s = 128; s > 0; s >>= 1) { if (tid < s) red[tid] = fmaxf(red[tid], red[tid + s]); __syncthreads(); }
        float gmax = red[0]; __syncthreads();
        float e_0 = __expf(l0 - gmax), e_1 = __expf(l1 - gmax), e_2 = __expf(l2 - gmax), e_3 = __expf(l3 - gmax);
        red[tid] = e_0 + e_1 + e_2 + e_3; __syncthreads();
        for (int s = 128; s > 0; s >>= 1) { if (tid < s) red[tid] += red[tid + s]; __syncthreads(); }
        float inv = 1.f / red[0]; __syncthreads();
        rs[0] += e_0 * inv; rs[1] += e_1 * inv; rs[2] += e_2 * inv; rs[3] += e_3 * inv;
        // top1
        float bv = l0; int bi = e0;
        if (l1 > bv) { bv = l1; bi = e0 + 1; }
        if (l2 > bv) { bv = l2; bi = e0 + 2; }
        if (l3 > bv) { bv = l3; bi = e0 + 3; }
        red[tid] = bv; redi[tid] = bi; __syncthreads();
        for (int s = 128; s > 0; s >>= 1) {
            if (tid < s) {
                float ov = red[tid + s]; int oi = redi[tid + s];
                if (ov > red[tid] || (ov == red[tid] && oi < redi[tid])) { red[tid] = ov; redi[tid] = oi; }
            }
            __syncthreads();
        }
        float v1 = red[0]; int i1 = redi[0]; __syncthreads();
        // top2
        float m0 = l0, m1 = l1, m2 = l2, m3 = l3;
        if      (i1 == e0)     m0 = -3e38f;
        else if (i1 == e0 + 1) m1 = -3e38f;
        else if (i1 == e0 + 2) m2 = -3e38f;
        else if (i1 == e0 + 3) m3 = -3e38f;
        bv = m0; bi = e0;
        if (m1 > bv) { bv = m1; bi = e0 + 1; }
        if (m2 > bv) { bv = m2; bi = e0 + 2; }
        if (m3 > bv) { bv = m3; bi = e0 + 3; }
        red[tid] = bv; redi[tid] = bi; __syncthreads();
        for (int s = 128; s > 0; s >>= 1) {
            if (tid < s) {
                float ov = red[tid + s]; int oi = redi[tid + s];
                if (ov > red[tid] || (ov == red[tid] && oi < redi[tid])) { red[tid] = ov; redi[tid] = oi; }
            }
            __syncthreads();
        }
        if (tid == 0) {
            float v2 = red[0]; int i2 = redi[0];
            float ga = __expf(v1 - gmax) * inv;
            float gb = __expf(v2 - gmax) * inv;
            float den = ga + gb + 1e-9f;
            g_idx1[t] = i1; g_idx2[t] = i2;
            g_g1[t] = ga / den; g_g2[t] = gb / den;
        }
        __syncthreads();
    }
    #pragma unroll
    for (int j = 0; j < 4; j++)
        if (rs[j] != 0.f) atomicAdd(&g_rawsum[b * 1024 + e0 + j], rs[j]);
}

// ---------------- capacity walk ----------------
__global__ void cap_k() {
    __shared__ int c1[1024], c2[1024];
    int b = blockIdx.x;
    for (int i = threadIdx.x; i < 1024; i += 256) { c1[i] = 0; c2[i] = 0; }
    __syncthreads();
    if (threadIdx.x == 0) {
        for (int n = 0; n < 256; n++) {
            int t = b * 256 + n; int e = g_idx1[t];
            if (c1[e] >= 4) g_g1[t] = 0.f;
            c1[e]++;
        }
        for (int n = 0; n < 256; n++) {
            int t = b * 256 + n; int e = g_idx2[t];
            int p = c2[e] + min(c1[e], 4);
            if (p >= 4) g_g2[t] = 0.f;
            c2[e]++;
        }
    }
    __syncthreads();
    for (int i = threadIdx.x; i < 1024; i += 256) g_cnt1[b * 1024 + i] = c1[i];
}

// ---------------- aux loss ----------------
__global__ void loss_k(float* __restrict__ aux) {
    __shared__ float red[256];
    float s = 0.f;
    for (int i = threadIdx.x; i < Bb * Ee; i += 256) s += g_rawsum[i] * (float)g_cnt1[i];
    red[threadIdx.x] = s; __syncthreads();
    for (int st = 128; st > 0; st >>= 1) { if (threadIdx.x < st) red[threadIdx.x] += red[threadIdx.x + st]; __syncthreads(); }
    if (threadIdx.x == 0) *aux = red[0] * (0.01f * (float)Ee / ((float)Bb * 256.f * 256.f));
}

// ---------------- scatter tokens to expert lists ----------------
__global__ void scatter_k() {
    int t = blockIdx.x * 256 + threadIdx.x;
    if (t >= NTOK) return;
    if (g_g1[t] != 0.f) {
        int e = g_idx1[t];
        int p = atomicAdd(&g_ecnt[e], 1);
        g_elist[e * 64 + p] = t * 2;
    }
    if (g_g2[t] != 0.f) {
        int e = g_idx2[t];
        int p = atomicAdd(&g_ecnt[e], 1);
        g_elist[e * 64 + p] = t * 2 + 1;
    }
}

// ---------------- expert compute: one block per expert ----------------
__global__ __launch_bounds__(256) void expert_k(const float* __restrict__ X, const float* __restrict__ w1,
                                                const float* __restrict__ w2) {
    int e = blockIdx.x;
    int nt = g_ecnt[e];
    if (nt == 0) return;
    __shared__ float xs[8][512];
    __shared__ float hs[8][32];
    int tid = threadIdx.x;
    for (int base = 0; base < nt; base += 8) {
        int nb = min(8, nt - base);
        for (int i = tid; i < nb * 512; i += 256) {
            int ti = i >> 9, d = i & 511;
            int a = g_elist[e * 64 + base + ti];
            xs[ti][d] = X[(a >> 1) * 512 + d];
        }
        __syncthreads();
        int ti = tid >> 5, hid = tid & 31;
        if (ti < nb) {
            float hv = 0.f;
            const float* wp = w1 + (size_t)e * 512 * 32 + hid;
            const float* xr = xs[ti];
            #pragma unroll 8
            for (int d = 0; d < 512; d++) hv += xr[d] * wp[d * 32];
            hs[ti][hid] = gelu_f(hv);
        }
        __syncthreads();
        const float* wq = w2 + (size_t)e * 32 * 512;
        for (int q = 0; q < nb; q++) {
            float s0 = 0.f, s1 = 0.f;
            #pragma unroll
            for (int j = 0; j < 32; j++) {
                float h = hs[q][j];
                s0 += h * wq[j * 512 + tid];
                s1 += h * wq[j * 512 + tid + 256];
            }
            int a = g_elist[e * 64 + base + q];
            g_eout[(size_t)a * 512 + tid]       = s0;
            g_eout[(size_t)a * 512 + tid + 256] = s1;
        }
        __syncthreads();
    }
}

// ---------------- combine MoE ----------------
__global__ void combine_k(float* __restrict__ o1, float* __restrict__ o2) {
    int i = blockIdx.x * 256 + threadIdx.x;
    int t = i >> 9;
    float g1 = g_g1[t], g2 = g_g2[t];
    float v = 0.f;
    if (g1 != 0.f) v += g1 * g_eout[(size_t)(t * 2) * 512 + (i & 511)];
    if (g2 != 0.f) v += g2 * g_eout[(size_t)(t * 2 + 1) * 512 + (i & 511)];
    o1[i] = v;
    o2[i] = v;
}

// ---------------- max pool ----------------
__global__ void pool_k(const float* __restrict__ y0, float* __restrict__ out) {
    int i = blockIdx.x * 256 + threadIdx.x;
    int j = i & 255, bc = i >> 8;
    const float* r = y0 + bc * 512;
    int l = 2 * j;
    float m = r[l];
    if (l > 0) m = fmaxf(m, r[l - 1]);
    m = fmaxf(m, r[l + 1]);
    out[i] = m;
}

// ---------------- launch ----------------
extern "C" void kernel_launch(void* const* d_in, const int* in_sizes, int n_in,
                              void* d_out, int out_size) {
    const float* x     = (const float*)d_in[0];
    const float* emb   = (const float*)d_in[1];
    const float* r1g1s = (const float*)d_in[2];
    const float* r1g1b = (const float*)d_in[3];
    const float* r1c1w = (const float*)d_in[4];
    const float* r1c1b = (const float*)d_in[5];
    const float* r1g2s = (const float*)d_in[6];
    const float* r1g2b = (const float*)d_in[7];
    const float* r1c2w = (const float*)d_in[8];
    const float* r1c2b = (const float*)d_in[9];
    const float* r2g1s = (const float*)d_in[10];
    const float* r2g1b = (const float*)d_in[11];
    const float* r2c1w = (const float*)d_in[12];
    const float* r2c1b = (const float*)d_in[13];
    const float* r2g2s = (const float*)d_in[14];
    const float* r2g2b = (const float*)d_in[15];
    const float* r2c2w = (const float*)d_in[16];
    const float* r2c2b = (const float*)d_in[17];
    const float* aw1   = (const float*)d_in[18];
    const float* ab1   = (const float*)d_in[19];
    const float* aw2   = (const float*)d_in[20];
    const float* ab2   = (const float*)d_in[21];
    const float* mwg   = (const float*)d_in[22];
    const float* mw1   = (const float*)d_in[23];
    const float* mw2   = (const float*)d_in[24];
    const float* ow    = (const float*)d_in[25];
    const float* ob    = (const float*)d_in[26];
    float* out = (float*)d_out;

    float *S1, *S2, *S3, *T;
    cudaGetSymbolAddress((void**)&S1, g_S1);
    cudaGetSymbolAddress((void**)&S2, g_S2);
    cudaGetSymbolAddress((void**)&S3, g_S3);
    cudaGetSymbolAddress((void**)&T,  g_T);

    cudaFuncSetAttribute(attn_k, cudaFuncAttributeMaxDynamicSharedMemorySize, 131072);
    cudaFuncSetAttribute(qkv_k,  cudaFuncAttributeMaxDynamicSharedMemorySize, 24 * QKV_GSTR * 4);

    // res_block 1 (x+emb fused into gn + conv residual)
    gn_k<<<256, 512>>>(x, emb, r1g1s, r1g1b, S2);
    conv16_k<<<dim3(2, 16, 8), 128>>>(S2, r1c1w, r1c1b, nullptr, nullptr, S3, 256);
    gn_k<<<256, 512>>>(S3, nullptr, r1g2s, r1g2b, S2);
    conv16_k<<<dim3(2, 16, 8), 128>>>(S2, r1c2w, r1c2b, x, emb, S3, 256);

    // attention
    qkv_k<<<dim3(8, 16), 384, 24 * QKV_GSTR * 4>>>(S3, aw1, ab1, T);
    attn_k<<<dim3(8, 8, 4), 128, 131072>>>(T, S2);
    oproj_k<<<dim3(8, 16), 128>>>(S2, aw2, ab2, emb, S1);

    // res_block 2
    gn_k<<<256, 512>>>(S1, nullptr, r2g1s, r2g1b, S2);
    conv16_k<<<dim3(2, 16, 8), 128>>>(S2, r2c1w, r2c1b, nullptr, nullptr, S3, 256);
    gn_k<<<256, 512>>>(S3, nullptr, r2g2s, r2g2b, S2);
    conv16_k<<<dim3(2, 16, 8), 128>>>(S2, r2c2w, r2c2b, S1, nullptr, S3, 256);

    // MoE
    zero_k<<<36, 256>>>();
    gate_k<<<256, 256>>>(S3, mwg);
    cap_k<<<8, 256>>>();
    loss_k<<<1, 256>>>(out + 2 * 1048576);
    scatter_k<<<8, 256>>>();
    expert_k<<<1024, 256>>>(S3, mw1, mw2);
    combine_k<<<4096, 256>>>(S2, out + 1048576);

    // output conv + maxpool
    conv16_k<<<dim3(2, 32, 8), 128>>>(S2, ow, ob, nullptr, nullptr, T, 512);
    pool_k<<<4096, 256>>>(T, out);
}

// round 13
// speedup vs baseline: 1.0287x; 1.0132x over previous
#include <cuda_runtime.h>
#include <math.h>

#define Bb 8
#define Cc 256
#define Ll 512
#define NG 32
#define NH 8
#define Ee 1024
#define NTOK (Bb*Cc)

typedef unsigned long long u64;

// ---------------- f32x2 helpers ----------------
__device__ __forceinline__ u64 fma2(u64 a, u64 b, u64 c) {
    u64 d; asm("fma.rn.f32x2 %0, %1, %2, %3;" : "=l"(d) : "l"(a), "l"(b), "l"(c)); return d;
}
__device__ __forceinline__ u64 mul2(u64 a, u64 b) {
    u64 d; asm("mul.rn.f32x2 %0, %1, %2;" : "=l"(d) : "l"(a), "l"(b)); return d;
}
__device__ __forceinline__ u64 add2(u64 a, u64 b) {
    u64 d; asm("add.rn.f32x2 %0, %1, %2;" : "=l"(d) : "l"(a), "l"(b)); return d;
}
__device__ __forceinline__ u64 pk2(float x, float y) {
    u64 d; asm("mov.b64 %0, {%1, %2};" : "=l"(d) : "r"(__float_as_uint(x)), "r"(__float_as_uint(y))); return d;
}
__device__ __forceinline__ float2 unpk2(u64 a) {
    unsigned int x, y; asm("mov.b64 {%0, %1}, %2;" : "=r"(x), "=r"(y) : "l"(a));
    return make_float2(__uint_as_float(x), __uint_as_float(y));
}

// ---------------- scratch ----------------
__device__ float g_S1[Bb*Cc*Ll];
__device__ float g_S2[Bb*Cc*Ll];
__device__ float g_S3[Bb*Cc*Ll];
__device__ float g_T [Bb*Ll*768];          // Q | K | V each 1048576 floats; also final conv out
__device__ float g_rawsum[Bb*Ee];
__device__ int   g_cnt1[Bb*Ee];
__device__ int   g_idx1[NTOK];
__device__ int   g_idx2[NTOK];
__device__ float g_g1[NTOK];
__device__ float g_g2[NTOK];
__device__ int   g_ecnt[Ee];
__device__ int   g_elist[Ee*64];
__device__ float g_eout[NTOK*2*512];

__device__ __forceinline__ float gelu_f(float x) {
    return 0.5f * x * (1.0f + erff(x * 0.70710678118654752f));
}

// ---------------- fused groupnorm (+opt add) + gelu: one CTA per (b,g) ----------------
__global__ __launch_bounds__(512) void gn_k(const float* __restrict__ in, const float* __restrict__ in2,
                                            const float* __restrict__ sc, const float* __restrict__ bi,
                                            float* __restrict__ out) {
    __shared__ float4 buf[1024];
    __shared__ float rs[16], rq[16];
    int bg = blockIdx.x, tid = threadIdx.x;
    const float4* p  = (const float4*)(in + bg * 4096);
    const float4* p2 = in2 ? (const float4*)(in2 + bg * 4096) : nullptr;
    float s = 0.f, q = 0.f;
    #pragma unroll
    for (int r = 0; r < 2; r++) {
        int i = tid + r * 512;
        float4 v = p[i];
        if (p2) {
            float4 w = p2[i];
            v.x += w.x; v.y += w.y; v.z += w.z; v.w += w.w;
        }
        buf[i] = v;
        s += v.x + v.y + v.z + v.w;
        q += v.x*v.x + v.y*v.y + v.z*v.z + v.w*v.w;
    }
    #pragma unroll
    for (int o = 16; o > 0; o >>= 1) {
        s += __shfl_down_sync(0xffffffffu, s, o);
        q += __shfl_down_sync(0xffffffffu, q, o);
    }
    if ((tid & 31) == 0) { rs[tid >> 5] = s; rq[tid >> 5] = q; }
    __syncthreads();
    if (tid < 32) {
        float s2 = (tid < 16) ? rs[tid] : 0.f;
        float q2 = (tid < 16) ? rq[tid] : 0.f;
        #pragma unroll
        for (int o = 8; o > 0; o >>= 1) {
            s2 += __shfl_down_sync(0xffffffffu, s2, o);
            q2 += __shfl_down_sync(0xffffffffu, q2, o);
        }
        if (tid == 0) {
            float mean = s2 * (1.f / 4096.f);
            float var  = q2 * (1.f / 4096.f) - mean * mean;
            rs[0] = mean;
            rq[0] = rsqrtf(var + 1e-5f);
        }
    }
    __syncthreads();
    float mean = rs[0], rstd = rq[0];
    float4* op = (float4*)(out + bg * 4096);
    int cbase = (bg & 31) * 8;
    #pragma unroll
    for (int r = 0; r < 2; r++) {
        int i = tid + r * 512;
        int c = cbase + (i >> 7);
        float a = rstd * sc[c];
        float b = bi[c] - mean * a;
        float4 v = buf[i];
        v.x = gelu_f(v.x * a + b);
        v.y = gelu_f(v.y * a + b);
        v.z = gelu_f(v.z * a + b);
        v.w = gelu_f(v.w * a + b);
        op[i] = v;
    }
}

// ---------------- conv1d k=3 smem-staged register-tiled: 64 co x 64 l per CTA ----------------
// grid: (8 l-tiles, Cout/64, 8 batch), 256 threads; thread = 4 co x 4 l
__global__ __launch_bounds__(256) void convT_k(
    const float* __restrict__ in, const float* __restrict__ w, const float* __restrict__ bias,
    const float* __restrict__ residA, const float* __restrict__ residB,
    float* __restrict__ out, int Cout) {
    __shared__ float2 xd[16 * 66];                 // chunk input, duplicated pairs (x,x)
    __shared__ __align__(16) float ws[48 * 68];    // chunk weights [r=ci*3+tap][co], row pad 68
    int b = blockIdx.z, co0 = blockIdx.y * 64, l0 = blockIdx.x * 64;
    int tid = threadIdx.x;
    int coq = tid & 15, lq = tid >> 4;
    u64 acc[2][4];
    {
        const float* bp = bias + co0 + coq * 4;
        u64 b0 = pk2(bp[0], bp[1]);
        u64 b1 = pk2(bp[2], bp[3]);
        #pragma unroll
        for (int l = 0; l < 4; l++) { acc[0][l] = b0; acc[1][l] = b1; }
    }
    const u64* xp = (const u64*)xd;
    const ulonglong2* wp2 = (const ulonglong2*)ws;
    for (int cib = 0; cib < 256; cib += 16) {
        // stage input (duplicated pairs), coalesced 66-float runs
        #pragma unroll
        for (int rr = 0; rr < 5; rr++) {
            int i = tid + rr * 256;
            if (i < 16 * 66) {
                int ci = i / 66, j = i - ci * 66;
                int l = l0 - 1 + j;
                float v = (l >= 0 && l < 512) ? __ldg(in + (b * 256 + cib + ci) * 512 + l) : 0.f;
                xd[i] = make_float2(v, v);
            }
        }
        // stage weights: ws[r*68 + cl] = w[(co0+cl)*768 + cib*3 + r]
        #pragma unroll
        for (int rr = 0; rr < 12; rr++) {
            int i = tid + rr * 256;
            int cl = i / 48, r = i - cl * 48;
            ws[r * 68 + cl] = __ldg(w + (co0 + cl) * 768 + cib * 3 + r);
        }
        __syncthreads();
        #pragma unroll 2
        for (int ci = 0; ci < 16; ci++) {
            u64 xv[6];
            #pragma unroll
            for (int j = 0; j < 6; j++) xv[j] = xp[ci * 66 + lq * 4 + j];
            #pragma unroll
            for (int tap = 0; tap < 3; tap++) {
                ulonglong2 wv = wp2[(ci * 3 + tap) * 17 + coq];
                #pragma unroll
                for (int l = 0; l < 4; l++) {
                    acc[0][l] = fma2(xv[l + tap], wv.x, acc[0][l]);
                    acc[1][l] = fma2(xv[l + tap], wv.y, acc[1][l]);
                }
            }
        }
        __syncthreads();
    }
    int base = (b * Cout + co0 + coq * 4) * 512 + l0 + lq * 4;
    #pragma unroll
    for (int cp = 0; cp < 2; cp++) {
        #pragma unroll
        for (int l = 0; l < 4; l++) {
            float2 v = unpk2(acc[cp][l]);
            int o0 = base + (cp * 2)     * 512 + l;
            int o1 = base + (cp * 2 + 1) * 512 + l;
            float r0 = 0.f, r1 = 0.f;
            if (residA) {
                r0 = residA[o0]; r1 = residA[o1];
                if (residB) { r0 += residB[o0]; r1 += residB[o1]; }
            }
            out[o0] = v.x + r0;
            out[o1] = v.y + r1;
        }
    }
}

// ---------------- QKV: computes tile, stages through smem, writes Q/K/V[b,h,l,32] ----------------
#define QKV_GSTR 545
__global__ __launch_bounds__(384) void qkv_k(const float* __restrict__ x, const float* __restrict__ w1,
                                             const float* __restrict__ b1, float* __restrict__ qkv) {
    extern __shared__ float sm[];
    int b = blockIdx.x, l0 = blockIdx.y * 32;
    for (int i = threadIdx.x; i < 256 * 32; i += 384) {
        int c = i >> 5, j = i & 31;
        sm[i] = x[(b * 256 + c) * 512 + l0 + j];
    }
    __syncthreads();
    int f = threadIdx.x;
    u64 A[16], B[16];
    {
        u64 ba = pk2(b1[f], b1[f]);
        u64 bb = pk2(b1[f + 384], b1[f + 384]);
        #pragma unroll
        for (int k = 0; k < 16; k++) { A[k] = ba; B[k] = bb; }
    }
    for (int c = 0; c < 256; c++) {
        float wa = w1[c * 768 + f];
        float wb = w1[c * 768 + f + 384];
        u64 ua = pk2(wa, wa), ub = pk2(wb, wb);
        const u64* xr = (const u64*)(sm + c * 32);
        #pragma unroll
        for (int k = 0; k < 16; k++) {
            u64 xv = xr[k];
            A[k] = fma2(xv, ua, A[k]);
            B[k] = fma2(xv, ub, B[k]);
        }
    }
    __syncthreads();
    int dd = f / 24, g = f - dd * 24;
    #pragma unroll
    for (int half = 0; half < 2; half++) {
        u64* R = half ? B : A;
        #pragma unroll
        for (int k = 0; k < 16; k++) {
            float2 v = unpk2(R[k]);
            sm[g * QKV_GSTR + (2*k)     * 17 + dd] = v.x;
            sm[g * QKV_GSTR + (2*k + 1) * 17 + dd] = v.y;
        }
        __syncthreads();
        #pragma unroll
        for (int rep = 0; rep < 2; rep++) {
            int j = threadIdx.x + rep * 384;
            int gg = j >> 5, l = j & 31;
            int h = gg / 3, kk = gg - h * 3;
            const float* srow = sm + gg * QKV_GSTR + l * 17;
            float4* dp = (float4*)(qkv + kk * 1048576 + (((b * 8) + h) * 512 + l0 + l) * 32 + half * 16);
            #pragma unroll
            for (int q4 = 0; q4 < 4; q4++)
                dp[q4] = make_float4(srow[q4*4], srow[q4*4+1], srow[q4*4+2], srow[q4*4+3]);
        }
        __syncthreads();
    }
}

// ---------------- attention: grid (b, h, 4 q-tiles), 128 threads ----------------
__global__ __launch_bounds__(128) void attn_k(const float* __restrict__ qkv, float* __restrict__ O) {
    extern __shared__ float sm[];
    float* Kf = sm;
    float* Vf = sm + 512 * 32;
    int b = blockIdx.x, h = blockIdx.y, qt = blockIdx.z, tid = threadIdx.x;
    int bh = b * 8 + h;
    {
        const float4* Ks = (const float4*)(qkv + 1048576 + bh * 16384);
        const float4* Vs = (const float4*)(qkv + 2097152 + bh * 16384);
        float4* Kd = (float4*)Kf;
        float4* Vd = (float4*)Vf;
        for (int i = tid; i < 4096; i += 128) {
            Kd[i] = Ks[i];
            Vd[i] = Vs[i];
        }
    }
    __syncthreads();
    int q = qt * 128 + tid;
    const float scale = 0.17677669529663687f;
    u64 q2[16];
    {
        const float* qb = qkv + (bh * 512 + q) * 32;
        #pragma unroll
        for (int i = 0; i < 16; i++)
            q2[i] = pk2(qb[2*i] * scale, qb[2*i + 1] * scale);
    }
    const u64* K2 = (const u64*)Kf;
    const u64* V2 = (const u64*)Vf;
    float m = -1e30f, s = 0.f;
    u64 acc2[16];
    #pragma unroll
    for (int i = 0; i < 16; i++) acc2[i] = 0ull;
    #pragma unroll 2
    for (int k = 0; k < 512; k++) {
        const u64* kr = K2 + k * 16;
        u64 d0 = mul2(q2[0], kr[0]);
        u64 d1 = mul2(q2[1], kr[1]);
        u64 d2 = mul2(q2[2], kr[2]);
        u64 d3 = mul2(q2[3], kr[3]);
        #pragma unroll
        for (int i = 4; i < 16; i += 4) {
            d0 = fma2(q2[i],     kr[i],     d0);
            d1 = fma2(q2[i + 1], kr[i + 1], d1);
            d2 = fma2(q2[i + 2], kr[i + 2], d2);
            d3 = fma2(q2[i + 3], kr[i + 3], d3);
        }
        d0 = add2(d0, d1);
        d2 = add2(d2, d3);
        d0 = add2(d0, d2);
        float2 dd = unpk2(d0);
        float dot = dd.x + dd.y;
        const u64* vr = V2 + k * 16;
        if (dot <= m) {
            float p = __expf(dot - m);
            s += p;
            u64 p2 = pk2(p, p);
            #pragma unroll
            for (int i = 0; i < 16; i++) acc2[i] = fma2(p2, vr[i], acc2[i]);
        } else {
            float corr = __expf(m - dot);
            m = dot;
            s = s * corr + 1.f;
            u64 c2 = pk2(corr, corr);
            #pragma unroll
            for (int i = 0; i < 16; i++) acc2[i] = fma2(acc2[i], c2, vr[i]);
        }
    }
    float inv = 1.f / s;
    float* op = O + (b * 512 + q) * 256 + h;
    #pragma unroll
    for (int i = 0; i < 16; i++) {
        float2 v = unpk2(acc2[i]);
        op[(2*i)     * 8] = v.x * inv;
        op[(2*i + 1) * 8] = v.y * inv;
    }
}

// ---------------- out projection ----------------
__global__ __launch_bounds__(128) void oproj_k(const float* __restrict__ O, const float* __restrict__ w2,
                                               const float* __restrict__ b2, const float* __restrict__ emb,
                                               float* __restrict__ out) {
    __shared__ float os[256][36];
    int b = blockIdx.x, l0 = blockIdx.y * 32;
    for (int i = threadIdx.x; i < 32 * 256; i += 128) {
        int c = i & 255, j = i >> 8;
        os[c][j] = O[(b * 512 + l0 + j) * 256 + c];
    }
    __syncthreads();
    int co = threadIdx.x;
    u64 A[16], B[16];
    {
        u64 ba = pk2(b2[co], b2[co]);
        u64 bb = pk2(b2[co + 128], b2[co + 128]);
        #pragma unroll
        for (int k = 0; k < 16; k++) { A[k] = ba; B[k] = bb; }
    }
    for (int c = 0; c < 256; c++) {
        float wa = w2[c * 256 + co];
        float wb = w2[c * 256 + co + 128];
        u64 ua = pk2(wa, wa), ub = pk2(wb, wb);
        const u64* xr = (const u64*)os[c];
        #pragma unroll
        for (int k = 0; k < 16; k++) {
            u64 xv = xr[k];
            A[k] = fma2(xv, ua, A[k]);
            B[k] = fma2(xv, ub, B[k]);
        }
    }
    #pragma unroll
    for (int k = 0; k < 16; k++) {
        float2 va = unpk2(A[k]);
        float2 vb = unpk2(B[k]);
        int oi  = (b * 256 + co) * 512 + l0 + 2*k;
        int oi2 = (b * 256 + co + 128) * 512 + l0 + 2*k;
        out[oi]      = va.x + emb[oi];
        out[oi + 1]  = va.y + emb[oi + 1];
        out[oi2]     = vb.x + emb[oi2];
        out[oi2 + 1] = vb.y + emb[oi2 + 1];
    }
}

// ---------------- zero rawsum + ecnt ----------------
__global__ void zero_k() {
    int i = blockIdx.x * 256 + threadIdx.x;
    if (i < Bb * Ee) g_rawsum[i] = 0.f;
    else if (i < Bb * Ee + Ee) g_ecnt[i - Bb * Ee] = 0;
}

// ---------------- gating: 4 tokens per block (R9 proven version) ----------------
__global__ __launch_bounds__(256) void gate_k(const float* __restrict__ X, const float* __restrict__ wg) {
    __shared__ float xv[4][512];
    __shared__ float red[256];
    __shared__ int redi[256];
    int t0 = blockIdx.x * 4, tid = threadIdx.x, b = t0 >> 8;
    for (int i = tid; i < 4 * 512; i += 256) {
        int tok = i >> 9, d = i & 511;
        xv[tok][d] = X[(t0 + tok) * 512 + d];
    }
    __syncthreads();
    int e0 = tid * 4;
    float acc[4][4];
    #pragma unroll
    for (int tk = 0; tk < 4; tk++)
        #pragma unroll
        for (int j = 0; j < 4; j++) acc[tk][j] = 0.f;
    for (int d = 0; d < 512; d++) {
        float4 w = *(const float4*)(wg + d * 1024 + e0);
        #pragma unroll
        for (int tk = 0; tk < 4; tk++) {
            float xd = xv[tk][d];
            acc[tk][0] += xd * w.x; acc[tk][1] += xd * w.y;
            acc[tk][2] += xd * w.z; acc[tk][3] += xd * w.w;
        }
    }
    float rs[4] = {0.f, 0.f, 0.f, 0.f};
    for (int tk = 0; tk < 4; tk++) {
        int t = t0 + tk;
        float l0 = acc[tk][0], l1 = acc[tk][1], l2 = acc[tk][2], l3 = acc[tk][3];
        float lm = fmaxf(fmaxf(l0, l1), fmaxf(l2, l3));
        red[tid] = lm; __syncthreads();
        for (int s = 128; s > 0; s >>= 1) { if (tid < s) red[tid] = fmaxf(red[tid], red[tid + s]); __syncthreads(); }
        float gmax = red[0]; __syncthreads();
        float e_0 = __expf(l0 - gmax), e_1 = __expf(l1 - gmax), e_2 = __expf(l2 - gmax), e_3 = __expf(l3 - gmax);
        red[tid] = e_0 + e_1 + e_2 + e_3; __syncthreads();
        for (int s = 128; s > 0; s >>= 1) { if (tid < s) red[tid] += red[tid + s]; __syncthreads(); }
        float inv = 1.f / red[0]; __syncthreads();
        rs[0] += e_0 * inv; rs[1] += e_1 * inv; rs[2] += e_2 * inv; rs[3] += e_3 * inv;
        float bv = l0; int bi = e0;
        if (l1 > bv) { bv = l1; bi = e0 + 1; }
        if (l2 > bv) { bv = l2; bi = e0 + 2; }
        if (l3 > bv) { bv = l3; bi = e0 + 3; }
        red[tid] = bv; redi[tid] = bi; __syncthreads();
        for (int s = 128; s > 0; s >>= 1) {
            if (tid < s) {
                float ov = red[tid + s]; int oi = redi[tid + s];
                if (ov > red[tid] || (ov == red[tid] && oi < redi[tid])) { red[tid] = ov; redi[tid] = oi; }
            }
            __syncthreads();
        }
        float v1 = red[0]; int i1 = redi[0]; __syncthreads();
        float m0 = l0, m1 = l1, m2 = l2, m3 = l3;
        if      (i1 == e0)     m0 = -3e38f;
        else if (i1 == e0 + 1) m1 = -3e38f;
        else if (i1 == e0 + 2) m2 = -3e38f;
        else if (i1 == e0 + 3) m3 = -3e38f;
        bv = m0; bi = e0;
        if (m1 > bv) { bv = m1; bi = e0 + 1; }
        if (m2 > bv) { bv = m2; bi = e0 + 2; }
        if (m3 > bv) { bv = m3; bi = e0 + 3; }
        red[tid] = bv; redi[tid] = bi; __syncthreads();
        for (int s = 128; s > 0; s >>= 1) {
            if (tid < s) {
                float ov = red[tid + s]; int oi = redi[tid + s];
                if (ov > red[tid] || (ov == red[tid] && oi < redi[tid])) { red[tid] = ov; redi[tid] = oi; }
            }
            __syncthreads();
        }
        if (tid == 0) {
            float v2 = red[0]; int i2 = redi[0];
            float ga = __expf(v1 - gmax) * inv;
            float gb = __expf(v2 - gmax) * inv;
            float den = ga + gb + 1e-9f;
            g_idx1[t] = i1; g_idx2[t] = i2;
            g_g1[t] = ga / den; g_g2[t] = gb / den;
        }
        __syncthreads();
    }
    #pragma unroll
    for (int j = 0; j < 4; j++)
        if (rs[j] != 0.f) atomicAdd(&g_rawsum[b * 1024 + e0 + j], rs[j]);
}

// ---------------- capacity walk ----------------
__global__ void cap_k() {
    __shared__ int c1[1024], c2[1024];
    int b = blockIdx.x;
    for (int i = threadIdx.x; i < 1024; i += 256) { c1[i] = 0; c2[i] = 0; }
    __syncthreads();
    if (threadIdx.x == 0) {
        for (int n = 0; n < 256; n++) {
            int t = b * 256 + n; int e = g_idx1[t];
            if (c1[e] >= 4) g_g1[t] = 0.f;
            c1[e]++;
        }
        for (int n = 0; n < 256; n++) {
            int t = b * 256 + n; int e = g_idx2[t];
            int p = c2[e] + min(c1[e], 4);
            if (p >= 4) g_g2[t] = 0.f;
            c2[e]++;
        }
    }
    __syncthreads();
    for (int i = threadIdx.x; i < 1024; i += 256) g_cnt1[b * 1024 + i] = c1[i];
}

// ---------------- aux loss ----------------
__global__ void loss_k(float* __restrict__ aux) {
    __shared__ float red[256];
    float s = 0.f;
    for (int i = threadIdx.x; i < Bb * Ee; i += 256) s += g_rawsum[i] * (float)g_cnt1[i];
    red[threadIdx.x] = s; __syncthreads();
    for (int st = 128; st > 0; st >>= 1) { if (threadIdx.x < st) red[threadIdx.x] += red[threadIdx.x + st]; __syncthreads(); }
    if (threadIdx.x == 0) *aux = red[0] * (0.01f * (float)Ee / ((float)Bb * 256.f * 256.f));
}

// ---------------- scatter tokens to expert lists ----------------
__global__ void scatter_k() {
    int t = blockIdx.x * 256 + threadIdx.x;
    if (t >= NTOK) return;
    if (g_g1[t] != 0.f) {
        int e = g_idx1[t];
        int p = atomicAdd(&g_ecnt[e], 1);
        g_elist[e * 64 + p] = t * 2;
    }
    if (g_g2[t] != 0.f) {
        int e = g_idx2[t];
        int p = atomicAdd(&g_ecnt[e], 1);
        g_elist[e * 64 + p] = t * 2 + 1;
    }
}

// ---------------- expert compute: one block per expert ----------------
__global__ __launch_bounds__(256) void expert_k(const float* __restrict__ X, const float* __restrict__ w1,
                                                const float* __restrict__ w2) {
    int e = blockIdx.x;
    int nt = g_ecnt[e];
    if (nt == 0) return;
    __shared__ float xs[8][512];
    __shared__ float hs[8][32];
    int tid = threadIdx.x;
    for (int base = 0; base < nt; base += 8) {
        int nb = min(8, nt - base);
        for (int i = tid; i < nb * 512; i += 256) {
            int ti = i >> 9, d = i & 511;
            int a = g_elist[e * 64 + base + ti];
            xs[ti][d] = X[(a >> 1) * 512 + d];
        }
        __syncthreads();
        int ti = tid >> 5, hid = tid & 31;
        if (ti < nb) {
            float hv = 0.f;
            const float* wp = w1 + (size_t)e * 512 * 32 + hid;
            const float* xr = xs[ti];
            #pragma unroll 8
            for (int d = 0; d < 512; d++) hv += xr[d] * wp[d * 32];
            hs[ti][hid] = gelu_f(hv);
        }
        __syncthreads();
        const float* wq = w2 + (size_t)e * 32 * 512;
        for (int q = 0; q < nb; q++) {
            float s0 = 0.f, s1 = 0.f;
            #pragma unroll
            for (int j = 0; j < 32; j++) {
                float h = hs[q][j];
                s0 += h * wq[j * 512 + tid];
                s1 += h * wq[j * 512 + tid + 256];
            }
            int a = g_elist[e * 64 + base + q];
            g_eout[(size_t)a * 512 + tid]       = s0;
            g_eout[(size_t)a * 512 + tid + 256] = s1;
        }
        __syncthreads();
    }
}

// ---------------- combine MoE ----------------
__global__ void combine_k(float* __restrict__ o1, float* __restrict__ o2) {
    int i = blockIdx.x * 256 + threadIdx.x;
    int t = i >> 9;
    float g1 = g_g1[t], g2 = g_g2[t];
    float v = 0.f;
    if (g1 != 0.f) v += g1 * g_eout[(size_t)(t * 2) * 512 + (i & 511)];
    if (g2 != 0.f) v += g2 * g_eout[(size_t)(t * 2 + 1) * 512 + (i & 511)];
    o1[i] = v;
    o2[i] = v;
}

// ---------------- max pool ----------------
__global__ void pool_k(const float* __restrict__ y0, float* __restrict__ out) {
    int i = blockIdx.x * 256 + threadIdx.x;
    int j = i & 255, bc = i >> 8;
    const float* r = y0 + bc * 512;
    int l = 2 * j;
    float m = r[l];
    if (l > 0) m = fmaxf(m, r[l - 1]);
    m = fmaxf(m, r[l + 1]);
    out[i] = m;
}

// ---------------- launch ----------------
extern "C" void kernel_launch(void* const* d_in, const int* in_sizes, int n_in,
                              void* d_out, int out_size) {
    const float* x     = (const float*)d_in[0];
    const float* emb   = (const float*)d_in[1];
    const float* r1g1s = (const float*)d_in[2];
    const float* r1g1b = (const float*)d_in[3];
    const float* r1c1w = (const float*)d_in[4];
    const float* r1c1b = (const float*)d_in[5];
    const float* r1g2s = (const float*)d_in[6];
    const float* r1g2b = (const float*)d_in[7];
    const float* r1c2w = (const float*)d_in[8];
    const float* r1c2b = (const float*)d_in[9];
    const float* r2g1s = (const float*)d_in[10];
    const float* r2g1b = (const float*)d_in[11];
    const float* r2c1w = (const float*)d_in[12];
    const float* r2c1b = (const float*)d_in[13];
    const float* r2g2s = (const float*)d_in[14];
    const float* r2g2b = (const float*)d_in[15];
    const float* r2c2w = (const float*)d_in[16];
    const float* r2c2b = (const float*)d_in[17];
    const float* aw1   = (const float*)d_in[18];
    const float* ab1   = (const float*)d_in[19];
    const float* aw2   = (const float*)d_in[20];
    const float* ab2   = (const float*)d_in[21];
    const float* mwg   = (const float*)d_in[22];
    const float* mw1   = (const float*)d_in[23];
    const float* mw2   = (const float*)d_in[24];
    const float* ow    = (const float*)d_in[25];
    const float* ob    = (const float*)d_in[26];
    float* out = (float*)d_out;

    float *S1, *S2, *S3, *T;
    cudaGetSymbolAddress((void**)&S1, g_S1);
    cudaGetSymbolAddress((void**)&S2, g_S2);
    cudaGetSymbolAddress((void**)&S3, g_S3);
    cudaGetSymbolAddress((void**)&T,  g_T);

    cudaFuncSetAttribute(attn_k, cudaFuncAttributeMaxDynamicSharedMemorySize, 131072);
    cudaFuncSetAttribute(qkv_k,  cudaFuncAttributeMaxDynamicSharedMemorySize, 24 * QKV_GSTR * 4);

    // res_block 1 (x+emb fused into gn + conv residual)
    gn_k<<<256, 512>>>(x, emb, r1g1s, r1g1b, S2);
    convT_k<<<dim3(8, 4, 8), 256>>>(S2, r1c1w, r1c1b, nullptr, nullptr, S3, 256);
    gn_k<<<256, 512>>>(S3, nullptr, r1g2s, r1g2b, S2);
    convT_k<<<dim3(8, 4, 8), 256>>>(S2, r1c2w, r1c2b, x, emb, S3, 256);

    // attention
    qkv_k<<<dim3(8, 16), 384, 24 * QKV_GSTR * 4>>>(S3, aw1, ab1, T);
    attn_k<<<dim3(8, 8, 4), 128, 131072>>>(T, S2);
    oproj_k<<<dim3(8, 16), 128>>>(S2, aw2, ab2, emb, S1);

    // res_block 2
    gn_k<<<256, 512>>>(S1, nullptr, r2g1s, r2g1b, S2);
    convT_k<<<dim3(8, 4, 8), 256>>>(S2, r2c1w, r2c1b, nullptr, nullptr, S3, 256);
    gn_k<<<256, 512>>>(S3, nullptr, r2g2s, r2g2b, S2);
    convT_k<<<dim3(8, 4, 8), 256>>>(S2, r2c2w, r2c2b, S1, nullptr, S3, 256);

    // MoE
    zero_k<<<36, 256>>>();
    gate_k<<<512, 256>>>(S3, mwg);
    cap_k<<<8, 256>>>();
    loss_k<<<1, 256>>>(out + 2 * 1048576);
    scatter_k<<<8, 256>>>();
    expert_k<<<1024, 256>>>(S3, mw1, mw2);
    combine_k<<<4096, 256>>>(S2, out + 1048576);

    // output conv + maxpool
    convT_k<<<dim3(8, 8, 8), 256>>>(S2, ow, ob, nullptr, nullptr, T, 512);
    pool_k<<<4096, 256>>>(T, out);
}

// round 14
// speedup vs baseline: 1.1171x; 1.0860x over previous
#include <cuda_runtime.h>
#include <math.h>

#define Bb 8
#define Cc 256
#define Ll 512
#define NG 32
#define NH 8
#define Ee 1024
#define NTOK (Bb*Cc)

typedef unsigned long long u64;

// ---------------- f32x2 helpers ----------------
__device__ __forceinline__ u64 fma2(u64 a, u64 b, u64 c) {
    u64 d; asm("fma.rn.f32x2 %0, %1, %2, %3;" : "=l"(d) : "l"(a), "l"(b), "l"(c)); return d;
}
__device__ __forceinline__ u64 mul2(u64 a, u64 b) {
    u64 d; asm("mul.rn.f32x2 %0, %1, %2;" : "=l"(d) : "l"(a), "l"(b)); return d;
}
__device__ __forceinline__ u64 add2(u64 a, u64 b) {
    u64 d; asm("add.rn.f32x2 %0, %1, %2;" : "=l"(d) : "l"(a), "l"(b)); return d;
}
__device__ __forceinline__ u64 pk2(float x, float y) {
    u64 d; asm("mov.b64 %0, {%1, %2};" : "=l"(d) : "r"(__float_as_uint(x)), "r"(__float_as_uint(y))); return d;
}
__device__ __forceinline__ float2 unpk2(u64 a) {
    unsigned int x, y; asm("mov.b64 {%0, %1}, %2;" : "=r"(x), "=r"(y) : "l"(a));
    return make_float2(__uint_as_float(x), __uint_as_float(y));
}

// ---------------- scratch ----------------
__device__ float g_S1[Bb*Cc*Ll];
__device__ float g_S2[Bb*Cc*Ll];
__device__ float g_S3[Bb*Cc*Ll];
__device__ float g_T [Bb*Ll*768];          // Q|K|V; later gate logits; later final conv out
__device__ float g_rawsum[Bb*Ee];
__device__ int   g_cnt1[Bb*Ee];
__device__ int   g_idx1[NTOK];
__device__ int   g_idx2[NTOK];
__device__ float g_g1[NTOK];
__device__ float g_g2[NTOK];
__device__ int   g_ecnt[Ee];
__device__ int   g_elist[Ee*64];
__device__ float g_eout[NTOK*2*512];

__device__ __forceinline__ float gelu_f(float x) {
    return 0.5f * x * (1.0f + erff(x * 0.70710678118654752f));
}

// ---------------- fused groupnorm (+opt add) + gelu ----------------
__global__ __launch_bounds__(512) void gn_k(const float* __restrict__ in, const float* __restrict__ in2,
                                            const float* __restrict__ sc, const float* __restrict__ bi,
                                            float* __restrict__ out) {
    __shared__ float4 buf[1024];
    __shared__ float rs[16], rq[16];
    int bg = blockIdx.x, tid = threadIdx.x;
    const float4* p  = (const float4*)(in + bg * 4096);
    const float4* p2 = in2 ? (const float4*)(in2 + bg * 4096) : nullptr;
    float s = 0.f, q = 0.f;
    #pragma unroll
    for (int r = 0; r < 2; r++) {
        int i = tid + r * 512;
        float4 v = p[i];
        if (p2) {
            float4 w = p2[i];
            v.x += w.x; v.y += w.y; v.z += w.z; v.w += w.w;
        }
        buf[i] = v;
        s += v.x + v.y + v.z + v.w;
        q += v.x*v.x + v.y*v.y + v.z*v.z + v.w*v.w;
    }
    #pragma unroll
    for (int o = 16; o > 0; o >>= 1) {
        s += __shfl_down_sync(0xffffffffu, s, o);
        q += __shfl_down_sync(0xffffffffu, q, o);
    }
    if ((tid & 31) == 0) { rs[tid >> 5] = s; rq[tid >> 5] = q; }
    __syncthreads();
    if (tid < 32) {
        float s2 = (tid < 16) ? rs[tid] : 0.f;
        float q2 = (tid < 16) ? rq[tid] : 0.f;
        #pragma unroll
        for (int o = 8; o > 0; o >>= 1) {
            s2 += __shfl_down_sync(0xffffffffu, s2, o);
            q2 += __shfl_down_sync(0xffffffffu, q2, o);
        }
        if (tid == 0) {
            float mean = s2 * (1.f / 4096.f);
            float var  = q2 * (1.f / 4096.f) - mean * mean;
            rs[0] = mean;
            rq[0] = rsqrtf(var + 1e-5f);
        }
    }
    __syncthreads();
    float mean = rs[0], rstd = rq[0];
    float4* op = (float4*)(out + bg * 4096);
    int cbase = (bg & 31) * 8;
    #pragma unroll
    for (int r = 0; r < 2; r++) {
        int i = tid + r * 512;
        int c = cbase + (i >> 7);
        float a = rstd * sc[c];
        float b = bi[c] - mean * a;
        float4 v = buf[i];
        v.x = gelu_f(v.x * a + b);
        v.y = gelu_f(v.y * a + b);
        v.z = gelu_f(v.z * a + b);
        v.w = gelu_f(v.w * a + b);
        op[i] = v;
    }
}

// ---------------- conv1d k=3 smem-staged register-tiled: 64 co x 64 l per CTA ----------------
__global__ __launch_bounds__(256) void convT_k(
    const float* __restrict__ in, const float* __restrict__ w, const float* __restrict__ bias,
    const float* __restrict__ residA, const float* __restrict__ residB,
    float* __restrict__ out, int Cout) {
    __shared__ float2 xd[16 * 66];
    __shared__ __align__(16) float ws[48 * 68];
    int b = blockIdx.z, co0 = blockIdx.y * 64, l0 = blockIdx.x * 64;
    int tid = threadIdx.x;
    int coq = tid & 15, lq = tid >> 4;
    u64 acc[2][4];
    {
        const float* bp = bias + co0 + coq * 4;
        u64 b0 = pk2(bp[0], bp[1]);
        u64 b1 = pk2(bp[2], bp[3]);
        #pragma unroll
        for (int l = 0; l < 4; l++) { acc[0][l] = b0; acc[1][l] = b1; }
    }
    const u64* xp = (const u64*)xd;
    const ulonglong2* wp2 = (const ulonglong2*)ws;
    for (int cib = 0; cib < 256; cib += 16) {
        #pragma unroll
        for (int rr = 0; rr < 5; rr++) {
            int i = tid + rr * 256;
            if (i < 16 * 66) {
                int ci = i / 66, j = i - ci * 66;
                int l = l0 - 1 + j;
                float v = (l >= 0 && l < 512) ? __ldg(in + (b * 256 + cib + ci) * 512 + l) : 0.f;
                xd[i] = make_float2(v, v);
            }
        }
        #pragma unroll
        for (int rr = 0; rr < 12; rr++) {
            int i = tid + rr * 256;
            int cl = i / 48, r = i - cl * 48;
            ws[r * 68 + cl] = __ldg(w + (co0 + cl) * 768 + cib * 3 + r);
        }
        __syncthreads();
        #pragma unroll 2
        for (int ci = 0; ci < 16; ci++) {
            u64 xv[6];
            #pragma unroll
            for (int j = 0; j < 6; j++) xv[j] = xp[ci * 66 + lq * 4 + j];
            #pragma unroll
            for (int tap = 0; tap < 3; tap++) {
                ulonglong2 wv = wp2[(ci * 3 + tap) * 17 + coq];
                #pragma unroll
                for (int l = 0; l < 4; l++) {
                    acc[0][l] = fma2(xv[l + tap], wv.x, acc[0][l]);
                    acc[1][l] = fma2(xv[l + tap], wv.y, acc[1][l]);
                }
            }
        }
        __syncthreads();
    }
    int base = (b * Cout + co0 + coq * 4) * 512 + l0 + lq * 4;
    #pragma unroll
    for (int cp = 0; cp < 2; cp++) {
        #pragma unroll
        for (int l = 0; l < 4; l++) {
            float2 v = unpk2(acc[cp][l]);
            int o0 = base + (cp * 2)     * 512 + l;
            int o1 = base + (cp * 2 + 1) * 512 + l;
            float r0 = 0.f, r1 = 0.f;
            if (residA) {
                r0 = residA[o0]; r1 = residA[o1];
                if (residB) { r0 += residB[o0]; r1 += residB[o1]; }
            }
            out[o0] = v.x + r0;
            out[o1] = v.y + r1;
        }
    }
}

// ---------------- QKV ----------------
#define QKV_GSTR 545
__global__ __launch_bounds__(384) void qkv_k(const float* __restrict__ x, const float* __restrict__ w1,
                                             const float* __restrict__ b1, float* __restrict__ qkv) {
    extern __shared__ float sm[];
    int b = blockIdx.x, l0 = blockIdx.y * 32;
    for (int i = threadIdx.x; i < 256 * 32; i += 384) {
        int c = i >> 5, j = i & 31;
        sm[i] = x[(b * 256 + c) * 512 + l0 + j];
    }
    __syncthreads();
    int f = threadIdx.x;
    u64 A[16], B[16];
    {
        u64 ba = pk2(b1[f], b1[f]);
        u64 bb = pk2(b1[f + 384], b1[f + 384]);
        #pragma unroll
        for (int k = 0; k < 16; k++) { A[k] = ba; B[k] = bb; }
    }
    for (int c = 0; c < 256; c++) {
        float wa = w1[c * 768 + f];
        float wb = w1[c * 768 + f + 384];
        u64 ua = pk2(wa, wa), ub = pk2(wb, wb);
        const u64* xr = (const u64*)(sm + c * 32);
        #pragma unroll
        for (int k = 0; k < 16; k++) {
            u64 xv = xr[k];
            A[k] = fma2(xv, ua, A[k]);
            B[k] = fma2(xv, ub, B[k]);
        }
    }
    __syncthreads();
    int dd = f / 24, g = f - dd * 24;
    #pragma unroll
    for (int half = 0; half < 2; half++) {
        u64* R = half ? B : A;
        #pragma unroll
        for (int k = 0; k < 16; k++) {
            float2 v = unpk2(R[k]);
            sm[g * QKV_GSTR + (2*k)     * 17 + dd] = v.x;
            sm[g * QKV_GSTR + (2*k + 1) * 17 + dd] = v.y;
        }
        __syncthreads();
        #pragma unroll
        for (int rep = 0; rep < 2; rep++) {
            int j = threadIdx.x + rep * 384;
            int gg = j >> 5, l = j & 31;
            int h = gg / 3, kk = gg - h * 3;
            const float* srow = sm + gg * QKV_GSTR + l * 17;
            float4* dp = (float4*)(qkv + kk * 1048576 + (((b * 8) + h) * 512 + l0 + l) * 32 + half * 16);
            #pragma unroll
            for (int q4 = 0; q4 < 4; q4++)
                dp[q4] = make_float4(srow[q4*4], srow[q4*4+1], srow[q4*4+2], srow[q4*4+3]);
        }
        __syncthreads();
    }
}

// ---------------- attention: grid (b, h, 2), 256 threads ----------------
__global__ __launch_bounds__(256) void attn_k(const float* __restrict__ qkv, float* __restrict__ O) {
    extern __shared__ float sm[];
    float* Kf = sm;
    float* Vf = sm + 512 * 32;
    int b = blockIdx.x, h = blockIdx.y, qt = blockIdx.z, tid = threadIdx.x;
    int bh = b * 8 + h;
    {
        const float4* Ks = (const float4*)(qkv + 1048576 + bh * 16384);
        const float4* Vs = (const float4*)(qkv + 2097152 + bh * 16384);
        float4* Kd = (float4*)Kf;
        float4* Vd = (float4*)Vf;
        for (int i = tid; i < 4096; i += 256) {
            Kd[i] = Ks[i];
            Vd[i] = Vs[i];
        }
    }
    __syncthreads();
    int q = qt * 256 + tid;
    const float scale = 0.17677669529663687f;
    u64 q2[16];
    {
        const float* qb = qkv + (bh * 512 + q) * 32;
        #pragma unroll
        for (int i = 0; i < 16; i++)
            q2[i] = pk2(qb[2*i] * scale, qb[2*i + 1] * scale);
    }
    const u64* K2 = (const u64*)Kf;
    const u64* V2 = (const u64*)Vf;
    float m = -1e30f, s = 0.f;
    u64 acc2[16];
    #pragma unroll
    for (int i = 0; i < 16; i++) acc2[i] = 0ull;
    #pragma unroll 2
    for (int k = 0; k < 512; k++) {
        const u64* kr = K2 + k * 16;
        u64 d0 = mul2(q2[0], kr[0]);
        u64 d1 = mul2(q2[1], kr[1]);
        u64 d2 = mul2(q2[2], kr[2]);
        u64 d3 = mul2(q2[3], kr[3]);
        #pragma unroll
        for (int i = 4; i < 16; i += 4) {
            d0 = fma2(q2[i],     kr[i],     d0);
            d1 = fma2(q2[i + 1], kr[i + 1], d1);
            d2 = fma2(q2[i + 2], kr[i + 2], d2);
            d3 = fma2(q2[i + 3], kr[i + 3], d3);
        }
        d0 = add2(d0, d1);
        d2 = add2(d2, d3);
        d0 = add2(d0, d2);
        float2 dd = unpk2(d0);
        float dot = dd.x + dd.y;
        const u64* vr = V2 + k * 16;
        if (dot <= m) {
            float p = __expf(dot - m);
            s += p;
            u64 p2 = pk2(p, p);
            #pragma unroll
            for (int i = 0; i < 16; i++) acc2[i] = fma2(p2, vr[i], acc2[i]);
        } else {
            float corr = __expf(m - dot);
            m = dot;
            s = s * corr + 1.f;
            u64 c2 = pk2(corr, corr);
            #pragma unroll
            for (int i = 0; i < 16; i++) acc2[i] = fma2(acc2[i], c2, vr[i]);
        }
    }
    float inv = 1.f / s;
    float* op = O + (b * 512 + q) * 256 + h;
    #pragma unroll
    for (int i = 0; i < 16; i++) {
        float2 v = unpk2(acc2[i]);
        op[(2*i)     * 8] = v.x * inv;
        op[(2*i + 1) * 8] = v.y * inv;
    }
}

// ---------------- out projection ----------------
__global__ __launch_bounds__(128) void oproj_k(const float* __restrict__ O, const float* __restrict__ w2,
                                               const float* __restrict__ b2, const float* __restrict__ emb,
                                               float* __restrict__ out) {
    __shared__ float os[256][36];
    int b = blockIdx.x, l0 = blockIdx.y * 32;
    for (int i = threadIdx.x; i < 32 * 256; i += 128) {
        int c = i & 255, j = i >> 8;
        os[c][j] = O[(b * 512 + l0 + j) * 256 + c];
    }
    __syncthreads();
    int co = threadIdx.x;
    u64 A[16], B[16];
    {
        u64 ba = pk2(b2[co], b2[co]);
        u64 bb = pk2(b2[co + 128], b2[co + 128]);
        #pragma unroll
        for (int k = 0; k < 16; k++) { A[k] = ba; B[k] = bb; }
    }
    for (int c = 0; c < 256; c++) {
        float wa = w2[c * 256 + co];
        float wb = w2[c * 256 + co + 128];
        u64 ua = pk2(wa, wa), ub = pk2(wb, wb);
        const u64* xr = (const u64*)os[c];
        #pragma unroll
        for (int k = 0; k < 16; k++) {
            u64 xv = xr[k];
            A[k] = fma2(xv, ua, A[k]);
            B[k] = fma2(xv, ub, B[k]);
        }
    }
    #pragma unroll
    for (int k = 0; k < 16; k++) {
        float2 va = unpk2(A[k]);
        float2 vb = unpk2(B[k]);
        int oi  = (b * 256 + co) * 512 + l0 + 2*k;
        int oi2 = (b * 256 + co + 128) * 512 + l0 + 2*k;
        out[oi]      = va.x + emb[oi];
        out[oi + 1]  = va.y + emb[oi + 1];
        out[oi2]     = vb.x + emb[oi2];
        out[oi2 + 1] = vb.y + emb[oi2 + 1];
    }
}

// ---------------- zero rawsum + ecnt ----------------
__global__ void zero_k() {
    int i = blockIdx.x * 256 + threadIdx.x;
    if (i < Bb * Ee) g_rawsum[i] = 0.f;
    else if (i < Bb * Ee + Ee) g_ecnt[i - Bb * Ee] = 0;
}

// ---------------- gate GEMM: logits[2048][1024]; CTA = 64 tok x 128 exp ----------------
__global__ __launch_bounds__(256) void ggemm_k(const float* __restrict__ X, const float* __restrict__ wg,
                                               float* __restrict__ L) {
    __shared__ float2 Xs[16][66];                       // duplicated token values
    __shared__ __align__(16) float Ws[16 * 132];        // [d][128 experts], row pad 132
    int t0 = blockIdx.x * 64, e0 = blockIdx.y * 128;
    int tid = threadIdx.x;
    int eq = tid & 15, tq = tid >> 4;
    u64 acc[4][4];
    #pragma unroll
    for (int t = 0; t < 4; t++)
        #pragma unroll
        for (int p = 0; p < 4; p++) acc[t][p] = 0ull;
    for (int db = 0; db < 512; db += 16) {
        {   // stage X: coalesced float4 per token row, transpose into Xs
            int tok = tid >> 2, f4 = tid & 3;
            float4 v = *(const float4*)(X + (t0 + tok) * 512 + db + f4 * 4);
            Xs[f4*4 + 0][tok] = make_float2(v.x, v.x);
            Xs[f4*4 + 1][tok] = make_float2(v.y, v.y);
            Xs[f4*4 + 2][tok] = make_float2(v.z, v.z);
            Xs[f4*4 + 3][tok] = make_float2(v.w, v.w);
        }
        #pragma unroll
        for (int pp = 0; pp < 2; pp++) {   // stage W
            int i = tid + pp * 256;
            int d = i >> 5, e4 = i & 31;
            float4 v = *(const float4*)(wg + (db + d) * 1024 + e0 + e4 * 4);
            *(float4*)(Ws + d * 132 + e4 * 4) = v;
        }
        __syncthreads();
        #pragma unroll 2
        for (int d = 0; d < 16; d++) {
            const ulonglong2* wr = (const ulonglong2*)(Ws + d * 132 + eq * 8);
            ulonglong2 w01 = wr[0];
            ulonglong2 w23 = wr[1];
            const u64* xr = (const u64*)Xs[d];
            #pragma unroll
            for (int t = 0; t < 4; t++) {
                u64 xv = xr[tq * 4 + t];
                acc[t][0] = fma2(xv, w01.x, acc[t][0]);
                acc[t][1] = fma2(xv, w01.y, acc[t][1]);
                acc[t][2] = fma2(xv, w23.x, acc[t][2]);
                acc[t][3] = fma2(xv, w23.y, acc[t][3]);
            }
        }
        __syncthreads();
    }
    #pragma unroll
    for (int t = 0; t < 4; t++) {
        float2* lp = (float2*)(L + (t0 + tq * 4 + t) * 1024 + e0 + eq * 8);
        #pragma unroll
        for (int p = 0; p < 4; p++) lp[p] = unpk2(acc[t][p]);
    }
}

// ---------------- softmax + top2: warp per token; 8 tokens per block ----------------
__global__ __launch_bounds__(256) void softtop_k(const float* __restrict__ L) {
    __shared__ float rsum[8][1024];
    int tid = threadIdx.x, warp = tid >> 5, lane = tid & 31;
    int t = blockIdx.x * 8 + warp;
    int b = t >> 8;
    float vals[32];
    {
        const float4* lp = (const float4*)(L + t * 1024 + lane * 32);
        #pragma unroll
        for (int j = 0; j < 8; j++) {
            float4 v = lp[j];
            vals[j*4] = v.x; vals[j*4+1] = v.y; vals[j*4+2] = v.z; vals[j*4+3] = v.w;
        }
    }
    // local top2 (ascending scan, strict > => first-occurrence ties)
    float v1 = -3.4e38f, v2 = -3.4e38f;
    int i1 = 0, i2 = 0;
    #pragma unroll
    for (int j = 0; j < 32; j++) {
        float v = vals[j];
        int idx = lane * 32 + j;
        if (v > v1) { v2 = v1; i2 = i1; v1 = v; i1 = idx; }
        else if (v > v2) { v2 = v; i2 = idx; }
    }
    // warp bfly merge of top2 sets (smaller index wins ties)
    #pragma unroll
    for (int o = 16; o > 0; o >>= 1) {
        float u1 = __shfl_xor_sync(0xffffffffu, v1, o);
        int   j1 = __shfl_xor_sync(0xffffffffu, i1, o);
        float u2 = __shfl_xor_sync(0xffffffffu, v2, o);
        int   j2 = __shfl_xor_sync(0xffffffffu, i2, o);
        bool b1 = (u1 > v1) || (u1 == v1 && j1 < i1);
        float n1, n2; int m1, m2;
        if (b1) {
            n1 = u1; m1 = j1;
            bool c = (v1 > u2) || (v1 == u2 && i1 < j2);
            n2 = c ? v1 : u2; m2 = c ? i1 : j2;
        } else {
            n1 = v1; m1 = i1;
            bool c = (u1 > v2) || (u1 == v2 && j1 < i2);
            n2 = c ? u1 : v2; m2 = c ? j1 : i2;
        }
        v1 = n1; i1 = m1; v2 = n2; i2 = m2;
    }
    float gmax = v1;
    float s = 0.f;
    #pragma unroll
    for (int j = 0; j < 32; j++) {
        vals[j] = __expf(vals[j] - gmax);
        s += vals[j];
    }
    #pragma unroll
    for (int o = 16; o > 0; o >>= 1) s += __shfl_xor_sync(0xffffffffu, s, o);
    float inv = 1.f / s;
    if (lane == 0) {
        float ga = inv;                      // exp(v1-gmax)=1
        float gb = __expf(v2 - gmax) * inv;
        float den = ga + gb + 1e-9f;
        g_idx1[t] = i1; g_idx2[t] = i2;
        g_g1[t] = ga / den; g_g2[t] = gb / den;
    }
    #pragma unroll
    for (int j = 0; j < 32; j++) rsum[warp][lane * 32 + j] = vals[j] * inv;
    __syncthreads();
    // flush: each thread sums 4 experts over 8 warps
    #pragma unroll
    for (int k = 0; k < 4; k++) {
        int e = tid * 4 + k;
        float acc = 0.f;
        #pragma unroll
        for (int w = 0; w < 8; w++) acc += rsum[w][e];
        atomicAdd(&g_rawsum[b * 1024 + e], acc);
    }
}

// ---------------- capacity walk + scatter (fused) ----------------
__global__ void capscat_k() {
    __shared__ int c1[1024], c2[1024];
    int b = blockIdx.x;
    for (int i = threadIdx.x; i < 1024; i += 256) { c1[i] = 0; c2[i] = 0; }
    __syncthreads();
    if (threadIdx.x == 0) {
        for (int n = 0; n < 256; n++) {
            int t = b * 256 + n; int e = g_idx1[t];
            if (c1[e] >= 4) g_g1[t] = 0.f;
            c1[e]++;
        }
        for (int n = 0; n < 256; n++) {
            int t = b * 256 + n; int e = g_idx2[t];
            int p = c2[e] + min(c1[e], 4);
            if (p >= 4) g_g2[t] = 0.f;
            c2[e]++;
        }
    }
    __syncthreads();
    for (int i = threadIdx.x; i < 1024; i += 256) g_cnt1[b * 1024 + i] = c1[i];
    // scatter this batch's tokens
    int n = threadIdx.x;
    int t = b * 256 + n;
    if (g_g1[t] != 0.f) {
        int e = g_idx1[t];
        int p = atomicAdd(&g_ecnt[e], 1);
        g_elist[e * 64 + p] = t * 2;
    }
    if (g_g2[t] != 0.f) {
        int e = g_idx2[t];
        int p = atomicAdd(&g_ecnt[e], 1);
        g_elist[e * 64 + p] = t * 2 + 1;
    }
}

// ---------------- aux loss ----------------
__global__ void loss_k(float* __restrict__ aux) {
    __shared__ float red[256];
    float s = 0.f;
    for (int i = threadIdx.x; i < Bb * Ee; i += 256) s += g_rawsum[i] * (float)g_cnt1[i];
    red[threadIdx.x] = s; __syncthreads();
    for (int st = 128; st > 0; st >>= 1) { if (threadIdx.x < st) red[threadIdx.x] += red[threadIdx.x + st]; __syncthreads(); }
    if (threadIdx.x == 0) *aux = red[0] * (0.01f * (float)Ee / ((float)Bb * 256.f * 256.f));
}

// ---------------- expert compute: one block per expert ----------------
__global__ __launch_bounds__(256) void expert_k(const float* __restrict__ X, const float* __restrict__ w1,
                                                const float* __restrict__ w2) {
    int e = blockIdx.x;
    int nt = g_ecnt[e];
    if (nt == 0) return;
    __shared__ float xs[8][512];
    __shared__ float hs[8][32];
    int tid = threadIdx.x;
    for (int base = 0; base < nt; base += 8) {
        int nb = min(8, nt - base);
        for (int i = tid; i < nb * 512; i += 256) {
            int ti = i >> 9, d = i & 511;
            int a = g_elist[e * 64 + base + ti];
            xs[ti][d] = X[(a >> 1) * 512 + d];
        }
        __syncthreads();
        int ti = tid >> 5, hid = tid & 31;
        if (ti < nb) {
            float hv = 0.f;
            const float* wp = w1 + (size_t)e * 512 * 32 + hid;
            const float* xr = xs[ti];
            #pragma unroll 8
            for (int d = 0; d < 512; d++) hv += xr[d] * wp[d * 32];
            hs[ti][hid] = gelu_f(hv);
        }
        __syncthreads();
        const float* wq = w2 + (size_t)e * 32 * 512;
        for (int q = 0; q < nb; q++) {
            float s0 = 0.f, s1 = 0.f;
            #pragma unroll
            for (int j = 0; j < 32; j++) {
                float h = hs[q][j];
                s0 += h * wq[j * 512 + tid];
                s1 += h * wq[j * 512 + tid + 256];
            }
            int a = g_elist[e * 64 + base + q];
            g_eout[(size_t)a * 512 + tid]       = s0;
            g_eout[(size_t)a * 512 + tid + 256] = s1;
        }
        __syncthreads();
    }
}

// ---------------- combine MoE ----------------
__global__ void combine_k(float* __restrict__ o1, float* __restrict__ o2) {
    int i = blockIdx.x * 256 + threadIdx.x;
    int t = i >> 9;
    float g1 = g_g1[t], g2 = g_g2[t];
    float v = 0.f;
    if (g1 != 0.f) v += g1 * g_eout[(size_t)(t * 2) * 512 + (i & 511)];
    if (g2 != 0.f) v += g2 * g_eout[(size_t)(t * 2 + 1) * 512 + (i & 511)];
    o1[i] = v;
    o2[i] = v;
}

// ---------------- max pool ----------------
__global__ void pool_k(const float* __restrict__ y0, float* __restrict__ out) {
    int i = blockIdx.x * 256 + threadIdx.x;
    int j = i & 255, bc = i >> 8;
    const float* r = y0 + bc * 512;
    int l = 2 * j;
    float m = r[l];
    if (l > 0) m = fmaxf(m, r[l - 1]);
    m = fmaxf(m, r[l + 1]);
    out[i] = m;
}

// ---------------- launch ----------------
extern "C" void kernel_launch(void* const* d_in, const int* in_sizes, int n_in,
                              void* d_out, int out_size) {
    const float* x     = (const float*)d_in[0];
    const float* emb   = (const float*)d_in[1];
    const float* r1g1s = (const float*)d_in[2];
    const float* r1g1b = (const float*)d_in[3];
    const float* r1c1w = (const float*)d_in[4];
    const float* r1c1b = (const float*)d_in[5];
    const float* r1g2s = (const float*)d_in[6];
    const float* r1g2b = (const float*)d_in[7];
    const float* r1c2w = (const float*)d_in[8];
    const float* r1c2b = (const float*)d_in[9];
    const float* r2g1s = (const float*)d_in[10];
    const float* r2g1b = (const float*)d_in[11];
    const float* r2c1w = (const float*)d_in[12];
    const float* r2c1b = (const float*)d_in[13];
    const float* r2g2s = (const float*)d_in[14];
    const float* r2g2b = (const float*)d_in[15];
    const float* r2c2w = (const float*)d_in[16];
    const float* r2c2b = (const float*)d_in[17];
    const float* aw1   = (const float*)d_in[18];
    const float* ab1   = (const float*)d_in[19];
    const float* aw2   = (const float*)d_in[20];
    const float* ab2   = (const float*)d_in[21];
    const float* mwg   = (const float*)d_in[22];
    const float* mw1   = (const float*)d_in[23];
    const float* mw2   = (const float*)d_in[24];
    const float* ow    = (const float*)d_in[25];
    const float* ob    = (const float*)d_in[26];
    float* out = (float*)d_out;

    float *S1, *S2, *S3, *T;
    cudaGetSymbolAddress((void**)&S1, g_S1);
    cudaGetSymbolAddress((void**)&S2, g_S2);
    cudaGetSymbolAddress((void**)&S3, g_S3);
    cudaGetSymbolAddress((void**)&T,  g_T);

    cudaFuncSetAttribute(attn_k, cudaFuncAttributeMaxDynamicSharedMemorySize, 131072);
    cudaFuncSetAttribute(qkv_k,  cudaFuncAttributeMaxDynamicSharedMemorySize, 24 * QKV_GSTR * 4);

    // res_block 1
    gn_k<<<256, 512>>>(x, emb, r1g1s, r1g1b, S2);
    convT_k<<<dim3(8, 4, 8), 256>>>(S2, r1c1w, r1c1b, nullptr, nullptr, S3, 256);
    gn_k<<<256, 512>>>(S3, nullptr, r1g2s, r1g2b, S2);
    convT_k<<<dim3(8, 4, 8), 256>>>(S2, r1c2w, r1c2b, x, emb, S3, 256);

    // attention
    qkv_k<<<dim3(8, 16), 384, 24 * QKV_GSTR * 4>>>(S3, aw1, ab1, T);
    attn_k<<<dim3(8, 8, 2), 256, 131072>>>(T, S2);
    oproj_k<<<dim3(8, 16), 128>>>(S2, aw2, ab2, emb, S1);

    // res_block 2
    gn_k<<<256, 512>>>(S1, nullptr, r2g1s, r2g1b, S2);
    convT_k<<<dim3(8, 4, 8), 256>>>(S2, r2c1w, r2c1b, nullptr, nullptr, S3, 256);
    gn_k<<<256, 512>>>(S3, nullptr, r2g2s, r2g2b, S2);
    convT_k<<<dim3(8, 4, 8), 256>>>(S2, r2c2w, r2c2b, S1, nullptr, S3, 256);

    // MoE
    zero_k<<<36, 256>>>();
    ggemm_k<<<dim3(32, 8), 256>>>(S3, mwg, T);
    softtop_k<<<256, 256>>>(T);
    capscat_k<<<8, 256>>>();
    loss_k<<<1, 256>>>(out + 2 * 1048576);
    expert_k<<<1024, 256>>>(S3, mw1, mw2);
    combine_k<<<4096, 256>>>(S2, out + 1048576);

    // output conv + maxpool
    convT_k<<<dim3(8, 8, 8), 256>>>(S2, ow, ob, nullptr, nullptr, T, 512);
    pool_k<<<4096, 256>>>(T, out);
}

// round 15
// speedup vs baseline: 1.1322x; 1.0134x over previous
#include <cuda_runtime.h>
#include <math.h>

#define Bb 8
#define Cc 256
#define Ll 512
#define NG 32
#define NH 8
#define Ee 1024
#define NTOK (Bb*Cc)

typedef unsigned long long u64;

// ---------------- f32x2 helpers ----------------
__device__ __forceinline__ u64 fma2(u64 a, u64 b, u64 c) {
    u64 d; asm("fma.rn.f32x2 %0, %1, %2, %3;" : "=l"(d) : "l"(a), "l"(b), "l"(c)); return d;
}
__device__ __forceinline__ u64 mul2(u64 a, u64 b) {
    u64 d; asm("mul.rn.f32x2 %0, %1, %2;" : "=l"(d) : "l"(a), "l"(b)); return d;
}
__device__ __forceinline__ u64 add2(u64 a, u64 b) {
    u64 d; asm("add.rn.f32x2 %0, %1, %2;" : "=l"(d) : "l"(a), "l"(b)); return d;
}
__device__ __forceinline__ u64 pk2(float x, float y) {
    u64 d; asm("mov.b64 %0, {%1, %2};" : "=l"(d) : "r"(__float_as_uint(x)), "r"(__float_as_uint(y))); return d;
}
__device__ __forceinline__ float2 unpk2(u64 a) {
    unsigned int x, y; asm("mov.b64 {%0, %1}, %2;" : "=r"(x), "=r"(y) : "l"(a));
    return make_float2(__uint_as_float(x), __uint_as_float(y));
}

// ---------------- scratch ----------------
__device__ float g_S1[Bb*Cc*Ll];
__device__ float g_S2[Bb*Cc*Ll];
__device__ float g_S3[Bb*Cc*Ll];
__device__ float g_T [Bb*Ll*768];          // Q|K|V; later gate logits; later final conv out
__device__ float g_rawsum[Bb*Ee];
__device__ int   g_cnt1[Bb*Ee];
__device__ int   g_idx1[NTOK];
__device__ int   g_idx2[NTOK];
__device__ float g_g1[NTOK];
__device__ float g_g2[NTOK];
__device__ int   g_ecnt[Ee];
__device__ int   g_elist[Ee*64];
__device__ float g_eout[NTOK*2*512];

__device__ __forceinline__ float gelu_f(float x) {
    return 0.5f * x * (1.0f + erff(x * 0.70710678118654752f));
}

// ---------------- fused groupnorm (+opt add) + gelu ----------------
__global__ __launch_bounds__(512) void gn_k(const float* __restrict__ in, const float* __restrict__ in2,
                                            const float* __restrict__ sc, const float* __restrict__ bi,
                                            float* __restrict__ out) {
    __shared__ float4 buf[1024];
    __shared__ float rs[16], rq[16];
    int bg = blockIdx.x, tid = threadIdx.x;
    const float4* p  = (const float4*)(in + bg * 4096);
    const float4* p2 = in2 ? (const float4*)(in2 + bg * 4096) : nullptr;
    float s = 0.f, q = 0.f;
    #pragma unroll
    for (int r = 0; r < 2; r++) {
        int i = tid + r * 512;
        float4 v = p[i];
        if (p2) {
            float4 w = p2[i];
            v.x += w.x; v.y += w.y; v.z += w.z; v.w += w.w;
        }
        buf[i] = v;
        s += v.x + v.y + v.z + v.w;
        q += v.x*v.x + v.y*v.y + v.z*v.z + v.w*v.w;
    }
    #pragma unroll
    for (int o = 16; o > 0; o >>= 1) {
        s += __shfl_down_sync(0xffffffffu, s, o);
        q += __shfl_down_sync(0xffffffffu, q, o);
    }
    if ((tid & 31) == 0) { rs[tid >> 5] = s; rq[tid >> 5] = q; }
    __syncthreads();
    if (tid < 32) {
        float s2 = (tid < 16) ? rs[tid] : 0.f;
        float q2 = (tid < 16) ? rq[tid] : 0.f;
        #pragma unroll
        for (int o = 8; o > 0; o >>= 1) {
            s2 += __shfl_down_sync(0xffffffffu, s2, o);
            q2 += __shfl_down_sync(0xffffffffu, q2, o);
        }
        if (tid == 0) {
            float mean = s2 * (1.f / 4096.f);
            float var  = q2 * (1.f / 4096.f) - mean * mean;
            rs[0] = mean;
            rq[0] = rsqrtf(var + 1e-5f);
        }
    }
    __syncthreads();
    float mean = rs[0], rstd = rq[0];
    float4* op = (float4*)(out + bg * 4096);
    int cbase = (bg & 31) * 8;
    #pragma unroll
    for (int r = 0; r < 2; r++) {
        int i = tid + r * 512;
        int c = cbase + (i >> 7);
        float a = rstd * sc[c];
        float b = bi[c] - mean * a;
        float4 v = buf[i];
        v.x = gelu_f(v.x * a + b);
        v.y = gelu_f(v.y * a + b);
        v.z = gelu_f(v.z * a + b);
        v.w = gelu_f(v.w * a + b);
        op[i] = v;
    }
}

// ---------------- conv1d k=3 smem-staged register-tiled + register-prefetch pipeline ----------------
// CTA = 64 co x 64 l, 256 threads, thread = 4 co x 4 l (f32x2)
__global__ __launch_bounds__(256) void convT_k(
    const float* __restrict__ in, const float* __restrict__ w, const float* __restrict__ bias,
    const float* __restrict__ residA, const float* __restrict__ residB,
    float* __restrict__ out, int Cout) {
    __shared__ float2 xd[16 * 66];
    __shared__ __align__(16) float ws[48 * 68];
    int b = blockIdx.z, co0 = blockIdx.y * 64, l0 = blockIdx.x * 64;
    int tid = threadIdx.x;
    int coq = tid & 15, lq = tid >> 4;
    u64 acc[2][4];
    {
        const float* bp = bias + co0 + coq * 4;
        u64 b0 = pk2(bp[0], bp[1]);
        u64 b1 = pk2(bp[2], bp[3]);
        #pragma unroll
        for (int l = 0; l < 4; l++) { acc[0][l] = b0; acc[1][l] = b1; }
    }
    // precomputed staging indices
    int xci[5], xl[5];
    #pragma unroll
    for (int rr = 0; rr < 5; rr++) {
        int i = tid + rr * 256;
        xci[rr] = i / 66;
        xl[rr]  = l0 - 1 + (i - xci[rr] * 66);
    }
    int wcl[12], wr[12];
    #pragma unroll
    for (int rr = 0; rr < 12; rr++) {
        int i = tid + rr * 256;
        wcl[rr] = i / 48;
        wr[rr]  = i - wcl[rr] * 48;
    }
    float xpre[5], wpre[12];
    // prefetch chunk 0
    #pragma unroll
    for (int rr = 0; rr < 5; rr++) {
        int i = tid + rr * 256;
        xpre[rr] = 0.f;
        if (i < 16 * 66 && xl[rr] >= 0 && xl[rr] < 512)
            xpre[rr] = __ldg(in + (b * 256 + xci[rr]) * 512 + xl[rr]);
    }
    #pragma unroll
    for (int rr = 0; rr < 12; rr++)
        wpre[rr] = __ldg(w + (co0 + wcl[rr]) * 768 + wr[rr]);

    const u64* xp = (const u64*)xd;
    const ulonglong2* wp2 = (const ulonglong2*)ws;
    for (int cb = 0; cb < 16; cb++) {
        // store prefetched chunk to smem
        #pragma unroll
        for (int rr = 0; rr < 5; rr++) {
            int i = tid + rr * 256;
            if (i < 16 * 66) xd[i] = make_float2(xpre[rr], xpre[rr]);
        }
        #pragma unroll
        for (int rr = 0; rr < 12; rr++)
            ws[wr[rr] * 68 + wcl[rr]] = wpre[rr];
        __syncthreads();
        // prefetch next chunk (overlaps with compute below)
        if (cb < 15) {
            int cib = (cb + 1) * 16;
            #pragma unroll
            for (int rr = 0; rr < 5; rr++) {
                int i = tid + rr * 256;
                xpre[rr] = 0.f;
                if (i < 16 * 66 && xl[rr] >= 0 && xl[rr] < 512)
                    xpre[rr] = __ldg(in + (b * 256 + cib + xci[rr]) * 512 + xl[rr]);
            }
            #pragma unroll
            for (int rr = 0; rr < 12; rr++)
                wpre[rr] = __ldg(w + (co0 + wcl[rr]) * 768 + cib * 3 + wr[rr]);
        }
        // compute on staged chunk
        #pragma unroll 2
        for (int ci = 0; ci < 16; ci++) {
            u64 xv[6];
            #pragma unroll
            for (int j = 0; j < 6; j++) xv[j] = xp[ci * 66 + lq * 4 + j];
            #pragma unroll
            for (int tap = 0; tap < 3; tap++) {
                ulonglong2 wv = wp2[(ci * 3 + tap) * 17 + coq];
                #pragma unroll
                for (int l = 0; l < 4; l++) {
                    acc[0][l] = fma2(xv[l + tap], wv.x, acc[0][l]);
                    acc[1][l] = fma2(xv[l + tap], wv.y, acc[1][l]);
                }
            }
        }
        __syncthreads();
    }
    int base = (b * Cout + co0 + coq * 4) * 512 + l0 + lq * 4;
    #pragma unroll
    for (int cp = 0; cp < 2; cp++) {
        #pragma unroll
        for (int l = 0; l < 4; l++) {
            float2 v = unpk2(acc[cp][l]);
            int o0 = base + (cp * 2)     * 512 + l;
            int o1 = base + (cp * 2 + 1) * 512 + l;
            float r0 = 0.f, r1 = 0.f;
            if (residA) {
                r0 = residA[o0]; r1 = residA[o1];
                if (residB) { r0 += residB[o0]; r1 += residB[o1]; }
            }
            out[o0] = v.x + r0;
            out[o1] = v.y + r1;
        }
    }
}

// ---------------- QKV ----------------
#define QKV_GSTR 545
__global__ __launch_bounds__(384) void qkv_k(const float* __restrict__ x, const float* __restrict__ w1,
                                             const float* __restrict__ b1, float* __restrict__ qkv) {
    extern __shared__ float sm[];
    int b = blockIdx.x, l0 = blockIdx.y * 32;
    for (int i = threadIdx.x; i < 256 * 32; i += 384) {
        int c = i >> 5, j = i & 31;
        sm[i] = x[(b * 256 + c) * 512 + l0 + j];
    }
    __syncthreads();
    int f = threadIdx.x;
    u64 A[16], B[16];
    {
        u64 ba = pk2(b1[f], b1[f]);
        u64 bb = pk2(b1[f + 384], b1[f + 384]);
        #pragma unroll
        for (int k = 0; k < 16; k++) { A[k] = ba; B[k] = bb; }
    }
    for (int c = 0; c < 256; c++) {
        float wa = w1[c * 768 + f];
        float wb = w1[c * 768 + f + 384];
        u64 ua = pk2(wa, wa), ub = pk2(wb, wb);
        const u64* xr = (const u64*)(sm + c * 32);
        #pragma unroll
        for (int k = 0; k < 16; k++) {
            u64 xv = xr[k];
            A[k] = fma2(xv, ua, A[k]);
            B[k] = fma2(xv, ub, B[k]);
        }
    }
    __syncthreads();
    int dd = f / 24, g = f - dd * 24;
    #pragma unroll
    for (int half = 0; half < 2; half++) {
        u64* R = half ? B : A;
        #pragma unroll
        for (int k = 0; k < 16; k++) {
            float2 v = unpk2(R[k]);
            sm[g * QKV_GSTR + (2*k)     * 17 + dd] = v.x;
            sm[g * QKV_GSTR + (2*k + 1) * 17 + dd] = v.y;
        }
        __syncthreads();
        #pragma unroll
        for (int rep = 0; rep < 2; rep++) {
            int j = threadIdx.x + rep * 384;
            int gg = j >> 5, l = j & 31;
            int h = gg / 3, kk = gg - h * 3;
            const float* srow = sm + gg * QKV_GSTR + l * 17;
            float4* dp = (float4*)(qkv + kk * 1048576 + (((b * 8) + h) * 512 + l0 + l) * 32 + half * 16);
            #pragma unroll
            for (int q4 = 0; q4 < 4; q4++)
                dp[q4] = make_float4(srow[q4*4], srow[q4*4+1], srow[q4*4+2], srow[q4*4+3]);
        }
        __syncthreads();
    }
}

// ---------------- attention: grid (b, h, 2), 256 threads ----------------
__global__ __launch_bounds__(256) void attn_k(const float* __restrict__ qkv, float* __restrict__ O) {
    extern __shared__ float sm[];
    float* Kf = sm;
    float* Vf = sm + 512 * 32;
    int b = blockIdx.x, h = blockIdx.y, qt = blockIdx.z, tid = threadIdx.x;
    int bh = b * 8 + h;
    {
        const float4* Ks = (const float4*)(qkv + 1048576 + bh * 16384);
        const float4* Vs = (const float4*)(qkv + 2097152 + bh * 16384);
        float4* Kd = (float4*)Kf;
        float4* Vd = (float4*)Vf;
        for (int i = tid; i < 4096; i += 256) {
            Kd[i] = Ks[i];
            Vd[i] = Vs[i];
        }
    }
    __syncthreads();
    int q = qt * 256 + tid;
    const float scale = 0.17677669529663687f;
    u64 q2[16];
    {
        const float* qb = qkv + (bh * 512 + q) * 32;
        #pragma unroll
        for (int i = 0; i < 16; i++)
            q2[i] = pk2(qb[2*i] * scale, qb[2*i + 1] * scale);
    }
    const u64* K2 = (const u64*)Kf;
    const u64* V2 = (const u64*)Vf;
    float m = -1e30f, s = 0.f;
    u64 acc2[16];
    #pragma unroll
    for (int i = 0; i < 16; i++) acc2[i] = 0ull;
    #pragma unroll 2
    for (int k = 0; k < 512; k++) {
        const u64* kr = K2 + k * 16;
        u64 d0 = mul2(q2[0], kr[0]);
        u64 d1 = mul2(q2[1], kr[1]);
        u64 d2 = mul2(q2[2], kr[2]);
        u64 d3 = mul2(q2[3], kr[3]);
        #pragma unroll
        for (int i = 4; i < 16; i += 4) {
            d0 = fma2(q2[i],     kr[i],     d0);
            d1 = fma2(q2[i + 1], kr[i + 1], d1);
            d2 = fma2(q2[i + 2], kr[i + 2], d2);
            d3 = fma2(q2[i + 3], kr[i + 3], d3);
        }
        d0 = add2(d0, d1);
        d2 = add2(d2, d3);
        d0 = add2(d0, d2);
        float2 dd = unpk2(d0);
        float dot = dd.x + dd.y;
        const u64* vr = V2 + k * 16;
        if (dot <= m) {
            float p = __expf(dot - m);
            s += p;
            u64 p2 = pk2(p, p);
            #pragma unroll
            for (int i = 0; i < 16; i++) acc2[i] = fma2(p2, vr[i], acc2[i]);
        } else {
            float corr = __expf(m - dot);
            m = dot;
            s = s * corr + 1.f;
            u64 c2 = pk2(corr, corr);
            #pragma unroll
            for (int i = 0; i < 16; i++) acc2[i] = fma2(acc2[i], c2, vr[i]);
        }
    }
    float inv = 1.f / s;
    float* op = O + (b * 512 + q) * 256 + h;
    #pragma unroll
    for (int i = 0; i < 16; i++) {
        float2 v = unpk2(acc2[i]);
        op[(2*i)     * 8] = v.x * inv;
        op[(2*i + 1) * 8] = v.y * inv;
    }
}

// ---------------- out projection ----------------
__global__ __launch_bounds__(128) void oproj_k(const float* __restrict__ O, const float* __restrict__ w2,
                                               const float* __restrict__ b2, const float* __restrict__ emb,
                                               float* __restrict__ out) {
    __shared__ float os[256][36];
    int b = blockIdx.x, l0 = blockIdx.y * 32;
    for (int i = threadIdx.x; i < 32 * 256; i += 128) {
        int c = i & 255, j = i >> 8;
        os[c][j] = O[(b * 512 + l0 + j) * 256 + c];
    }
    __syncthreads();
    int co = threadIdx.x;
    u64 A[16], B[16];
    {
        u64 ba = pk2(b2[co], b2[co]);
        u64 bb = pk2(b2[co + 128], b2[co + 128]);
        #pragma unroll
        for (int k = 0; k < 16; k++) { A[k] = ba; B[k] = bb; }
    }
    for (int c = 0; c < 256; c++) {
        float wa = w2[c * 256 + co];
        float wb = w2[c * 256 + co + 128];
        u64 ua = pk2(wa, wa), ub = pk2(wb, wb);
        const u64* xr = (const u64*)os[c];
        #pragma unroll
        for (int k = 0; k < 16; k++) {
            u64 xv = xr[k];
            A[k] = fma2(xv, ua, A[k]);
            B[k] = fma2(xv, ub, B[k]);
        }
    }
    #pragma unroll
    for (int k = 0; k < 16; k++) {
        float2 va = unpk2(A[k]);
        float2 vb = unpk2(B[k]);
        int oi  = (b * 256 + co) * 512 + l0 + 2*k;
        int oi2 = (b * 256 + co + 128) * 512 + l0 + 2*k;
        out[oi]      = va.x + emb[oi];
        out[oi + 1]  = va.y + emb[oi + 1];
        out[oi2]     = vb.x + emb[oi2];
        out[oi2 + 1] = vb.y + emb[oi2 + 1];
    }
}

// ---------------- zero rawsum + ecnt ----------------
__global__ void zero_k() {
    int i = blockIdx.x * 256 + threadIdx.x;
    if (i < Bb * Ee) g_rawsum[i] = 0.f;
    else if (i < Bb * Ee + Ee) g_ecnt[i - Bb * Ee] = 0;
}

// ---------------- gate GEMM: logits[2048][1024]; CTA = 64 tok x 128 exp ----------------
__global__ __launch_bounds__(256) void ggemm_k(const float* __restrict__ X, const float* __restrict__ wg,
                                               float* __restrict__ L) {
    __shared__ float2 Xs[16][66];
    __shared__ __align__(16) float Ws[16 * 132];
    int t0 = blockIdx.x * 64, e0 = blockIdx.y * 128;
    int tid = threadIdx.x;
    int eq = tid & 15, tq = tid >> 4;
    u64 acc[4][4];
    #pragma unroll
    for (int t = 0; t < 4; t++)
        #pragma unroll
        for (int p = 0; p < 4; p++) acc[t][p] = 0ull;
    for (int db = 0; db < 512; db += 16) {
        {
            int tok = tid >> 2, f4 = tid & 3;
            float4 v = *(const float4*)(X + (t0 + tok) * 512 + db + f4 * 4);
            Xs[f4*4 + 0][tok] = make_float2(v.x, v.x);
            Xs[f4*4 + 1][tok] = make_float2(v.y, v.y);
            Xs[f4*4 + 2][tok] = make_float2(v.z, v.z);
            Xs[f4*4 + 3][tok] = make_float2(v.w, v.w);
        }
        #pragma unroll
        for (int pp = 0; pp < 2; pp++) {
            int i = tid + pp * 256;
            int d = i >> 5, e4 = i & 31;
            float4 v = *(const float4*)(wg + (db + d) * 1024 + e0 + e4 * 4);
            *(float4*)(Ws + d * 132 + e4 * 4) = v;
        }
        __syncthreads();
        #pragma unroll 2
        for (int d = 0; d < 16; d++) {
            const ulonglong2* wr = (const ulonglong2*)(Ws + d * 132 + eq * 8);
            ulonglong2 w01 = wr[0];
            ulonglong2 w23 = wr[1];
            const u64* xr = (const u64*)Xs[d];
            #pragma unroll
            for (int t = 0; t < 4; t++) {
                u64 xv = xr[tq * 4 + t];
                acc[t][0] = fma2(xv, w01.x, acc[t][0]);
                acc[t][1] = fma2(xv, w01.y, acc[t][1]);
                acc[t][2] = fma2(xv, w23.x, acc[t][2]);
                acc[t][3] = fma2(xv, w23.y, acc[t][3]);
            }
        }
        __syncthreads();
    }
    #pragma unroll
    for (int t = 0; t < 4; t++) {
        float2* lp = (float2*)(L + (t0 + tq * 4 + t) * 1024 + e0 + eq * 8);
        #pragma unroll
        for (int p = 0; p < 4; p++) lp[p] = unpk2(acc[t][p]);
    }
}

// ---------------- softmax + top2: warp per token; 8 tokens per block ----------------
__global__ __launch_bounds__(256) void softtop_k(const float* __restrict__ L) {
    __shared__ float rsum[8][1024];
    int tid = threadIdx.x, warp = tid >> 5, lane = tid & 31;
    int t = blockIdx.x * 8 + warp;
    int b = t >> 8;
    float vals[32];
    {
        const float4* lp = (const float4*)(L + t * 1024 + lane * 32);
        #pragma unroll
        for (int j = 0; j < 8; j++) {
            float4 v = lp[j];
            vals[j*4] = v.x; vals[j*4+1] = v.y; vals[j*4+2] = v.z; vals[j*4+3] = v.w;
        }
    }
    float v1 = -3.4e38f, v2 = -3.4e38f;
    int i1 = 0, i2 = 0;
    #pragma unroll
    for (int j = 0; j < 32; j++) {
        float v = vals[j];
        int idx = lane * 32 + j;
        if (v > v1) { v2 = v1; i2 = i1; v1 = v; i1 = idx; }
        else if (v > v2) { v2 = v; i2 = idx; }
    }
    #pragma unroll
    for (int o = 16; o > 0; o >>= 1) {
        float u1 = __shfl_xor_sync(0xffffffffu, v1, o);
        int   j1 = __shfl_xor_sync(0xffffffffu, i1, o);
        float u2 = __shfl_xor_sync(0xffffffffu, v2, o);
        int   j2 = __shfl_xor_sync(0xffffffffu, i2, o);
        bool b1 = (u1 > v1) || (u1 == v1 && j1 < i1);
        float n1, n2; int m1, m2;
        if (b1) {
            n1 = u1; m1 = j1;
            bool c = (v1 > u2) || (v1 == u2 && i1 < j2);
            n2 = c ? v1 : u2; m2 = c ? i1 : j2;
        } else {
            n1 = v1; m1 = i1;
            bool c = (u1 > v2) || (u1 == v2 && j1 < i2);
            n2 = c ? u1 : v2; m2 = c ? j1 : i2;
        }
        v1 = n1; i1 = m1; v2 = n2; i2 = m2;
    }
    float gmax = v1;
    float s = 0.f;
    #pragma unroll
    for (int j = 0; j < 32; j++) {
        vals[j] = __expf(vals[j] - gmax);
        s += vals[j];
    }
    #pragma unroll
    for (int o = 16; o > 0; o >>= 1) s += __shfl_xor_sync(0xffffffffu, s, o);
    float inv = 1.f / s;
    if (lane == 0) {
        float ga = inv;
        float gb = __expf(v2 - gmax) * inv;
        float den = ga + gb + 1e-9f;
        g_idx1[t] = i1; g_idx2[t] = i2;
        g_g1[t] = ga / den; g_g2[t] = gb / den;
    }
    #pragma unroll
    for (int j = 0; j < 32; j++) rsum[warp][lane * 32 + j] = vals[j] * inv;
    __syncthreads();
    #pragma unroll
    for (int k = 0; k < 4; k++) {
        int e = tid * 4 + k;
        float acc = 0.f;
        #pragma unroll
        for (int w = 0; w < 8; w++) acc += rsum[w][e];
        atomicAdd(&g_rawsum[b * 1024 + e], acc);
    }
}

// ---------------- capacity walk + scatter (fused) ----------------
__global__ void capscat_k() {
    __shared__ int c1[1024], c2[1024];
    int b = blockIdx.x;
    for (int i = threadIdx.x; i < 1024; i += 256) { c1[i] = 0; c2[i] = 0; }
    __syncthreads();
    if (threadIdx.x == 0) {
        for (int n = 0; n < 256; n++) {
            int t = b * 256 + n; int e = g_idx1[t];
            if (c1[e] >= 4) g_g1[t] = 0.f;
            c1[e]++;
        }
        for (int n = 0; n < 256; n++) {
            int t = b * 256 + n; int e = g_idx2[t];
            int p = c2[e] + min(c1[e], 4);
            if (p >= 4) g_g2[t] = 0.f;
            c2[e]++;
        }
    }
    __syncthreads();
    for (int i = threadIdx.x; i < 1024; i += 256) g_cnt1[b * 1024 + i] = c1[i];
    int n = threadIdx.x;
    int t = b * 256 + n;
    if (g_g1[t] != 0.f) {
        int e = g_idx1[t];
        int p = atomicAdd(&g_ecnt[e], 1);
        g_elist[e * 64 + p] = t * 2;
    }
    if (g_g2[t] != 0.f) {
        int e = g_idx2[t];
        int p = atomicAdd(&g_ecnt[e], 1);
        g_elist[e * 64 + p] = t * 2 + 1;
    }
}

// ---------------- aux loss ----------------
__global__ void loss_k(float* __restrict__ aux) {
    __shared__ float red[256];
    float s = 0.f;
    for (int i = threadIdx.x; i < Bb * Ee; i += 256) s += g_rawsum[i] * (float)g_cnt1[i];
    red[threadIdx.x] = s; __syncthreads();
    for (int st = 128; st > 0; st >>= 1) { if (threadIdx.x < st) red[threadIdx.x] += red[threadIdx.x + st]; __syncthreads(); }
    if (threadIdx.x == 0) *aux = red[0] * (0.01f * (float)Ee / ((float)Bb * 256.f * 256.f));
}

// ---------------- expert compute: one block per expert ----------------
__global__ __launch_bounds__(256) void expert_k(const float* __restrict__ X, const float* __restrict__ w1,
                                                const float* __restrict__ w2) {
    int e = blockIdx.x;
    int nt = g_ecnt[e];
    if (nt == 0) return;
    __shared__ float xs[8][512];
    __shared__ float hs[8][32];
    int tid = threadIdx.x;
    for (int base = 0; base < nt; base += 8) {
        int nb = min(8, nt - base);
        for (int i = tid; i < nb * 512; i += 256) {
            int ti = i >> 9, d = i & 511;
            int a = g_elist[e * 64 + base + ti];
            xs[ti][d] = X[(a >> 1) * 512 + d];
        }
        __syncthreads();
        int ti = tid >> 5, hid = tid & 31;
        if (ti < nb) {
            float hv = 0.f;
            const float* wp = w1 + (size_t)e * 512 * 32 + hid;
            const float* xr = xs[ti];
            #pragma unroll 8
            for (int d = 0; d < 512; d++) hv += xr[d] * wp[d * 32];
            hs[ti][hid] = gelu_f(hv);
        }
        __syncthreads();
        const float* wq = w2 + (size_t)e * 32 * 512;
        for (int q = 0; q < nb; q++) {
            float s0 = 0.f, s1 = 0.f;
            #pragma unroll
            for (int j = 0; j < 32; j++) {
                float h = hs[q][j];
                s0 += h * wq[j * 512 + tid];
                s1 += h * wq[j * 512 + tid + 256];
            }
            int a = g_elist[e * 64 + base + q];
            g_eout[(size_t)a * 512 + tid]       = s0;
            g_eout[(size_t)a * 512 + tid + 256] = s1;
        }
        __syncthreads();
    }
}

// ---------------- combine MoE ----------------
__global__ void combine_k(float* __restrict__ o1, float* __restrict__ o2) {
    int i = blockIdx.x * 256 + threadIdx.x;
    int t = i >> 9;
    float g1 = g_g1[t], g2 = g_g2[t];
    float v = 0.f;
    if (g1 != 0.f) v += g1 * g_eout[(size_t)(t * 2) * 512 + (i & 511)];
    if (g2 != 0.f) v += g2 * g_eout[(size_t)(t * 2 + 1) * 512 + (i & 511)];
    o1[i] = v;
    o2[i] = v;
}

// ---------------- max pool ----------------
__global__ void pool_k(const float* __restrict__ y0, float* __restrict__ out) {
    int i = blockIdx.x * 256 + threadIdx.x;
    int j = i & 255, bc = i >> 8;
    const float* r = y0 + bc * 512;
    int l = 2 * j;
    float m = r[l];
    if (l > 0) m = fmaxf(m, r[l - 1]);
    m = fmaxf(m, r[l + 1]);
    out[i] = m;
}

// ---------------- launch ----------------
extern "C" void kernel_launch(void* const* d_in, const int* in_sizes, int n_in,
                              void* d_out, int out_size) {
    const float* x     = (const float*)d_in[0];
    const float* emb   = (const float*)d_in[1];
    const float* r1g1s = (const float*)d_in[2];
    const float* r1g1b = (const float*)d_in[3];
    const float* r1c1w = (const float*)d_in[4];
    const float* r1c1b = (const float*)d_in[5];
    const float* r1g2s = (const float*)d_in[6];
    const float* r1g2b = (const float*)d_in[7];
    const float* r1c2w = (const float*)d_in[8];
    const float* r1c2b = (const float*)d_in[9];
    const float* r2g1s = (const float*)d_in[10];
    const float* r2g1b = (const float*)d_in[11];
    const float* r2c1w = (const float*)d_in[12];
    const float* r2c1b = (const float*)d_in[13];
    const float* r2g2s = (const float*)d_in[14];
    const float* r2g2b = (const float*)d_in[15];
    const float* r2c2w = (const float*)d_in[16];
    const float* r2c2b = (const float*)d_in[17];
    const float* aw1   = (const float*)d_in[18];
    const float* ab1   = (const float*)d_in[19];
    const float* aw2   = (const float*)d_in[20];
    const float* ab2   = (const float*)d_in[21];
    const float* mwg   = (const float*)d_in[22];
    const float* mw1   = (const float*)d_in[23];
    const float* mw2   = (const float*)d_in[24];
    const float* ow    = (const float*)d_in[25];
    const float* ob    = (const float*)d_in[26];
    float* out = (float*)d_out;

    float *S1, *S2, *S3, *T;
    cudaGetSymbolAddress((void**)&S1, g_S1);
    cudaGetSymbolAddress((void**)&S2, g_S2);
    cudaGetSymbolAddress((void**)&S3, g_S3);
    cudaGetSymbolAddress((void**)&T,  g_T);

    cudaFuncSetAttribute(attn_k, cudaFuncAttributeMaxDynamicSharedMemorySize, 131072);
    cudaFuncSetAttribute(qkv_k,  cudaFuncAttributeMaxDynamicSharedMemorySize, 24 * QKV_GSTR * 4);

    // res_block 1
    gn_k<<<256, 512>>>(x, emb, r1g1s, r1g1b, S2);
    convT_k<<<dim3(8, 4, 8), 256>>>(S2, r1c1w, r1c1b, nullptr, nullptr, S3, 256);
    gn_k<<<256, 512>>>(S3, nullptr, r1g2s, r1g2b, S2);
    convT_k<<<dim3(8, 4, 8), 256>>>(S2, r1c2w, r1c2b, x, emb, S3, 256);

    // attention
    qkv_k<<<dim3(8, 16), 384, 24 * QKV_GSTR * 4>>>(S3, aw1, ab1, T);
    attn_k<<<dim3(8, 8, 2), 256, 131072>>>(T, S2);
    oproj_k<<<dim3(8, 16), 128>>>(S2, aw2, ab2, emb, S1);

    // res_block 2
    gn_k<<<256, 512>>>(S1, nullptr, r2g1s, r2g1b, S2);
    convT_k<<<dim3(8, 4, 8), 256>>>(S2, r2c1w, r2c1b, nullptr, nullptr, S3, 256);
    gn_k<<<256, 512>>>(S3, nullptr, r2g2s, r2g2b, S2);
    convT_k<<<dim3(8, 4, 8), 256>>>(S2, r2c2w, r2c2b, S1, nullptr, S3, 256);

    // MoE
    zero_k<<<36, 256>>>();
    ggemm_k<<<dim3(32, 8), 256>>>(S3, mwg, T);
    softtop_k<<<256, 256>>>(T);
    capscat_k<<<8, 256>>>();
    loss_k<<<1, 256>>>(out + 2 * 1048576);
    expert_k<<<1024, 256>>>(S3, mw1, mw2);
    combine_k<<<4096, 256>>>(S2, out + 1048576);

    // output conv + maxpool
    convT_k<<<dim3(8, 8, 8), 256>>>(S2, ow, ob, nullptr, nullptr, T, 512);
    pool_k<<<4096, 256>>>(T, out);
}